// round 8
// baseline (speedup 1.0000x reference)
#include <cuda_runtime.h>
#include <cuda_bf16.h>
#include <math.h>

// Problem constants
#define BATCH 2
#define SLEN 2048
#define HID 4096
#define NHEAD 32
#define HDIM 128
#define MROWS (BATCH * SLEN)       // 4096
#define QKV_N (3 * HID)            // 12288

// ---------------- scratch (no allocations allowed) ----------------
__device__ float g_qkv[(size_t)MROWS * QKV_N];   // 201 MB
__device__ __nv_bfloat16 g_hs_hi[(size_t)MROWS * HID];
__device__ __nv_bfloat16 g_hs_lo[(size_t)MROWS * HID];
__device__ __nv_bfloat16 g_ctx_hi[(size_t)MROWS * HID];
__device__ __nv_bfloat16 g_ctx_lo[(size_t)MROWS * HID];
__device__ __nv_bfloat16 g_wqkv_hi[(size_t)QKV_N * HID];   // transposed [N][K]
__device__ __nv_bfloat16 g_wqkv_lo[(size_t)QKV_N * HID];
__device__ __nv_bfloat16 g_wo_hi[(size_t)HID * HID];       // transposed [N][K]
__device__ __nv_bfloat16 g_wo_lo[(size_t)HID * HID];
__device__ __nv_bfloat16 g_q_hi[(size_t)MROWS * HID];
__device__ __nv_bfloat16 g_q_lo[(size_t)MROWS * HID];
__device__ __nv_bfloat16 g_k_hi[(size_t)MROWS * HID];
__device__ __nv_bfloat16 g_k_lo[(size_t)MROWS * HID];
__device__ __nv_bfloat16 g_v_hi[(size_t)MROWS * HID];
__device__ __nv_bfloat16 g_v_lo[(size_t)MROWS * HID];

// ---------------- helpers ----------------
__device__ __forceinline__ void split_bf16(float x, __nv_bfloat16& h, __nv_bfloat16& l)
{
    h = __float2bfloat16(x);
    l = __float2bfloat16(x - __bfloat162float(h));
}

__device__ __forceinline__ unsigned pack_bf16x2(float x, float y)
{
    unsigned r;
    asm("cvt.rn.bf16x2.f32 %0, %1, %2;" : "=r"(r) : "f"(y), "f"(x));
    return r;
}

#define CP_ASYNC16(dst, src) \
    asm volatile("cp.async.cg.shared.global [%0], [%1], 16;\n" :: "r"(dst), "l"(src))
#define CP_COMMIT() asm volatile("cp.async.commit_group;\n" ::: "memory")
#define CP_WAIT(n)  asm volatile("cp.async.wait_group %0;\n" :: "n"(n) : "memory")

#define LDSM_X4(r0, r1, r2, r3, addr) \
    asm volatile("ldmatrix.sync.aligned.m8n8.x4.shared.b16 {%0,%1,%2,%3}, [%4];" \
        : "=r"(r0), "=r"(r1), "=r"(r2), "=r"(r3) : "r"(addr))

__device__ __forceinline__ void mma_bf16(float* c, const unsigned* a, const unsigned* b)
{
    asm volatile(
        "mma.sync.aligned.m16n8k16.row.col.f32.bf16.bf16.f32 "
        "{%0,%1,%2,%3},{%4,%5,%6,%7},{%8,%9},{%0,%1,%2,%3};"
        : "+f"(c[0]), "+f"(c[1]), "+f"(c[2]), "+f"(c[3])
        : "r"(a[0]), "r"(a[1]), "r"(a[2]), "r"(a[3]), "r"(b[0]), "r"(b[1]));
}

// ---------------- split / transpose kernels ----------------
__global__ void split_kernel(const float* __restrict__ src,
                             __nv_bfloat16* __restrict__ hi,
                             __nv_bfloat16* __restrict__ lo, int n4)
{
    int i = blockIdx.x * blockDim.x + threadIdx.x;
    if (i >= n4) return;
    float4 v = ((const float4*)src)[i];
    __nv_bfloat16 h0, h1, h2, h3, l0, l1, l2, l3;
    split_bf16(v.x, h0, l0); split_bf16(v.y, h1, l1);
    split_bf16(v.z, h2, l2); split_bf16(v.w, h3, l3);
    __nv_bfloat162* hp = (__nv_bfloat162*)(hi + (size_t)i * 4);
    __nv_bfloat162* lp = (__nv_bfloat162*)(lo + (size_t)i * 4);
    hp[0] = __nv_bfloat162(h0, h1); hp[1] = __nv_bfloat162(h2, h3);
    lp[0] = __nv_bfloat162(l0, l1); lp[1] = __nv_bfloat162(l2, l3);
}

__global__ void transpose_split_kernel(const float* __restrict__ W,
                                       __nv_bfloat16* __restrict__ hi,
                                       __nv_bfloat16* __restrict__ lo,
                                       int K, int N)
{
    __shared__ float t[32][33];
    const int n0 = blockIdx.x * 32;
    const int k0 = blockIdx.y * 32;
    const int tx = threadIdx.x;
    const int ty = threadIdx.y;
#pragma unroll
    for (int j = 0; j < 32; j += 8)
        t[ty + j][tx] = W[(size_t)(k0 + ty + j) * N + n0 + tx];
    __syncthreads();
#pragma unroll
    for (int j = 0; j < 32; j += 8) {
        float x = t[tx][ty + j];
        __nv_bfloat16 h, l;
        split_bf16(x, h, l);
        size_t o = (size_t)(n0 + ty + j) * K + k0 + tx;
        hi[o] = h;
        lo[o] = l;
    }
}

// ================= bf16-split tensor-core GEMM (128x256 tile, 3-stage) =================
#define BM 128
#define BN 256
#define BK 32
#define SSTRIDE 40
#define A_ELEMS (128 * SSTRIDE)        // 5120
#define B_ELEMS (256 * SSTRIDE)        // 10240
#define OFF_AHI 0
#define OFF_ALO A_ELEMS
#define OFF_BHI (2 * A_ELEMS)
#define OFF_BLO (2 * A_ELEMS + B_ELEMS)
#define STAGE_ELEMS (2 * A_ELEMS + 2 * B_ELEMS)   // 30720
#define NSTAGE 3
#define GEMM_SMEM_BYTES (NSTAGE * STAGE_ELEMS * 2)  // 184320

__global__ __launch_bounds__(512, 1)
void gemm_bf16split_kernel(const __nv_bfloat16* __restrict__ Ahi,
                           const __nv_bfloat16* __restrict__ Alo,
                           const __nv_bfloat16* __restrict__ Bhi,
                           const __nv_bfloat16* __restrict__ Blo,
                           const float* __restrict__ bias, float* __restrict__ C,
                           int M, int N, int K)
{
    extern __shared__ __nv_bfloat16 sm[];
    const int tid = threadIdx.x;
    const int wid = tid >> 5;
    const int lane = tid & 31;
    const int grp = lane >> 2;
    const int qid = lane & 3;
    const int warp_m = wid >> 3;   // 0..1 (64 rows)
    const int warp_n = wid & 7;    // 0..7 (32 cols)

    const int m0 = blockIdx.y * BM;
    const int n0 = blockIdx.x * BN;

    float acc[4][4][4];
#pragma unroll
    for (int i = 0; i < 4; i++)
#pragma unroll
        for (int j = 0; j < 4; j++)
#pragma unroll
            for (int r = 0; r < 4; r++) acc[i][j][r] = 0.f;

    unsigned smem_base = (unsigned)__cvta_generic_to_shared(sm);
    const int NIT = K / BK;

    // ldmatrix per-lane element offsets
    const unsigned a_elem = (unsigned)((warp_m * 64 + (lane & 15)) * SSTRIDE
                                       + ((lane >> 4) & 1) * 8);
    const unsigned b_elem = (unsigned)((warp_n * 32 + ((lane >> 4) & 1) * 8 + (lane & 7)) * SSTRIDE
                                       + ((lane >> 3) & 1) * 8);

    // per-thread loader coords
    const int a_row = tid >> 2;          // 0..127
    const int a_c   = tid & 3;           // 16B chunk

    auto load_stage = [&](int st, int k0) {
        unsigned sb = smem_base + (unsigned)(st * STAGE_ELEMS) * 2u;
        // A hi/lo: one 16B chunk per thread per array
        CP_ASYNC16(sb + (unsigned)(OFF_AHI + a_row * SSTRIDE + a_c * 8) * 2u,
                   Ahi + (size_t)(m0 + a_row) * K + k0 + a_c * 8);
        CP_ASYNC16(sb + (unsigned)(OFF_ALO + a_row * SSTRIDE + a_c * 8) * 2u,
                   Alo + (size_t)(m0 + a_row) * K + k0 + a_c * 8);
        // B hi/lo: two chunks per thread per array
#pragma unroll
        for (int p = 0; p < 2; p++) {
            int i = p * 512 + tid;
            int row = i >> 2, c = i & 3;
            CP_ASYNC16(sb + (unsigned)(OFF_BHI + row * SSTRIDE + c * 8) * 2u,
                       Bhi + (size_t)(n0 + row) * K + k0 + c * 8);
            CP_ASYNC16(sb + (unsigned)(OFF_BLO + row * SSTRIDE + c * 8) * 2u,
                       Blo + (size_t)(n0 + row) * K + k0 + c * 8);
        }
    };

    load_stage(0, 0);
    CP_COMMIT();
    load_stage(1, BK);
    CP_COMMIT();

    int st = 0;
    for (int it = 0; it < NIT; it++) {
        if (it + 2 < NIT) {
            int st2 = st + 2; if (st2 >= NSTAGE) st2 -= NSTAGE;
            load_stage(st2, (it + 2) * BK);
            CP_COMMIT();
            CP_WAIT(2);
        } else if (it + 1 < NIT) {
            CP_WAIT(1);
        } else {
            CP_WAIT(0);
        }
        __syncthreads();

        const unsigned stg = smem_base + (unsigned)(st * STAGE_ELEMS) * 2u;
        const unsigned a_lo_off = (unsigned)A_ELEMS * 2u;
        const unsigned b_lo_off = (unsigned)B_ELEMS * 2u;
        const unsigned b_base = stg + (unsigned)OFF_BHI * 2u;

#pragma unroll
        for (int kk = 0; kk < 2; kk++) {
            unsigned ahi[4][4], alo[4][4], bh[2][4], bl[2][4];
#pragma unroll
            for (int mt = 0; mt < 4; mt++) {
                unsigned ad = stg + (a_elem + (unsigned)(mt * 16 * SSTRIDE + kk * 16)) * 2u;
                LDSM_X4(ahi[mt][0], ahi[mt][1], ahi[mt][2], ahi[mt][3], ad);
                LDSM_X4(alo[mt][0], alo[mt][1], alo[mt][2], alo[mt][3], ad + a_lo_off);
            }
#pragma unroll
            for (int p = 0; p < 2; p++) {
                unsigned bd = b_base + (b_elem + (unsigned)(p * 16 * SSTRIDE + kk * 16)) * 2u;
                LDSM_X4(bh[p][0], bh[p][1], bh[p][2], bh[p][3], bd);
                LDSM_X4(bl[p][0], bl[p][1], bl[p][2], bl[p][3], bd + b_lo_off);
            }
            // hi * hi
#pragma unroll
            for (int mt = 0; mt < 4; mt++)
#pragma unroll
                for (int p = 0; p < 2; p++) {
                    mma_bf16(acc[mt][2 * p + 0], ahi[mt], &bh[p][0]);
                    mma_bf16(acc[mt][2 * p + 1], ahi[mt], &bh[p][2]);
                }
            // hi * lo
#pragma unroll
            for (int mt = 0; mt < 4; mt++)
#pragma unroll
                for (int p = 0; p < 2; p++) {
                    mma_bf16(acc[mt][2 * p + 0], ahi[mt], &bl[p][0]);
                    mma_bf16(acc[mt][2 * p + 1], ahi[mt], &bl[p][2]);
                }
            // lo * hi
#pragma unroll
            for (int mt = 0; mt < 4; mt++)
#pragma unroll
                for (int p = 0; p < 2; p++) {
                    mma_bf16(acc[mt][2 * p + 0], alo[mt], &bh[p][0]);
                    mma_bf16(acc[mt][2 * p + 1], alo[mt], &bh[p][2]);
                }
        }
        __syncthreads();
        if (++st == NSTAGE) st = 0;
    }

#pragma unroll
    for (int mt = 0; mt < 4; mt++) {
        const int mrow = m0 + warp_m * 64 + mt * 16 + grp;
#pragma unroll
        for (int nt = 0; nt < 4; nt++) {
            const int col = n0 + warp_n * 32 + nt * 8 + 2 * qid;
            float b0 = bias ? bias[col] : 0.f;
            float b1 = bias ? bias[col + 1] : 0.f;
            float2 v0 = make_float2(acc[mt][nt][0] + b0, acc[mt][nt][1] + b1);
            float2 v1 = make_float2(acc[mt][nt][2] + b0, acc[mt][nt][3] + b1);
            *(float2*)(C + (size_t)mrow * N + col) = v0;
            *(float2*)(C + (size_t)(mrow + 8) * N + col) = v1;
        }
    }
}

// ---------------- fused RoPE + split + relayout ----------------
__global__ void rope_split_kernel(const float* __restrict__ qkv,
                                  const int* __restrict__ positions)
{
    int idx = blockIdx.x * blockDim.x + threadIdx.x;
    if (idx >= MROWS * NHEAD * 64) return;
    const int i = idx & 63;
    const int h = (idx >> 6) & 31;
    const int m = idx >> 11;
    const int b = m >> 11;
    const int s = m & 2047;

    const float pos = (float)positions[m];
    const float inv_freq = powf(10000.0f, -(float)i / 64.0f);
    const float ang = pos * inv_freq;
    const float c = cosf(ang);
    const float sn = sinf(ang);

    const float* row = qkv + (size_t)m * QKV_N + h * HDIM;
    const size_t hb = ((size_t)((b * NHEAD + h) * SLEN) + s) * HDIM;

    {
        float x1 = row[i], x2 = row[i + 64];
        float y1 = x1 * c - x2 * sn;
        float y2 = x2 * c + x1 * sn;
        __nv_bfloat16 h1, l1, h2, l2;
        split_bf16(y1, h1, l1); split_bf16(y2, h2, l2);
        g_q_hi[hb + i] = h1; g_q_hi[hb + i + 64] = h2;
        g_q_lo[hb + i] = l1; g_q_lo[hb + i + 64] = l2;
    }
    {
        float x1 = row[HID + i], x2 = row[HID + i + 64];
        float y1 = x1 * c - x2 * sn;
        float y2 = x2 * c + x1 * sn;
        __nv_bfloat16 h1, l1, h2, l2;
        split_bf16(y1, h1, l1); split_bf16(y2, h2, l2);
        g_k_hi[hb + i] = h1; g_k_hi[hb + i + 64] = h2;
        g_k_lo[hb + i] = l1; g_k_lo[hb + i + 64] = l2;
    }
    {
        float x1 = row[2 * HID + i], x2 = row[2 * HID + i + 64];
        __nv_bfloat16 h1, l1, h2, l2;
        split_bf16(x1, h1, l1); split_bf16(x2, h2, l2);
        g_v_hi[hb + i] = h1; g_v_hi[hb + i + 64] = h2;
        g_v_lo[hb + i] = l1; g_v_lo[hb + i + 64] = l2;
    }
}

// ---------------- tensor-core flash attention (bf16-split, causal) ----------------
#define AQT 128
#define AKT 64
#define QST 136
#define KST 136
#define VST 72
#define SM_QHI 0
#define SM_QLO (SM_QHI + AQT * QST)
#define SM_KHI (SM_QLO + AQT * QST)
#define SM_KLO (SM_KHI + AKT * KST)
#define SM_VHI (SM_KLO + AKT * KST)
#define SM_VLO (SM_VHI + AQT * VST)
#define ATT_SMEM_ELEMS (SM_VLO + AQT * VST)
#define ATT_SMEM_BYTES (ATT_SMEM_ELEMS * 2)   // 141312

__global__ __launch_bounds__(256)
void flash_mma_kernel(const __nv_bfloat16* __restrict__ qh, const __nv_bfloat16* __restrict__ ql,
                      const __nv_bfloat16* __restrict__ kh, const __nv_bfloat16* __restrict__ kl,
                      const __nv_bfloat16* __restrict__ vh, const __nv_bfloat16* __restrict__ vl,
                      __nv_bfloat16* __restrict__ ctx_hi, __nv_bfloat16* __restrict__ ctx_lo)
{
    extern __shared__ __nv_bfloat16 sma[];
    const int qt = blockIdx.x;
    const int h  = blockIdx.y;
    const int b  = blockIdx.z;
    const int tid = threadIdx.x;
    const int wid = tid >> 5;
    const int lane = tid & 31;
    const int grp = lane >> 2;
    const int qid = lane & 3;
    const size_t hb = ((size_t)(b * NHEAD + h)) * SLEN * HDIM;
    unsigned sbase = (unsigned)__cvta_generic_to_shared(sma);
    const float scale = 0.08838834764831845f;

    {
        const __nv_bfloat16* g = qh + hb + (size_t)qt * AQT * HDIM;
#pragma unroll
        for (int p = 0; p < 8; p++) {
            int i = p * 256 + tid;
            int row = i >> 4, c = i & 15;
            CP_ASYNC16(sbase + (unsigned)(SM_QHI + row * QST + c * 8) * 2u, g + row * HDIM + c * 8);
        }
        g = ql + hb + (size_t)qt * AQT * HDIM;
#pragma unroll
        for (int p = 0; p < 8; p++) {
            int i = p * 256 + tid;
            int row = i >> 4, c = i & 15;
            CP_ASYNC16(sbase + (unsigned)(SM_QLO + row * QST + c * 8) * 2u, g + row * HDIM + c * 8);
        }
        CP_COMMIT();
    }

    float m0 = -1e30f, m1 = -1e30f, l0 = 0.f, l1 = 0.f;
    float o[16][4];
#pragma unroll
    for (int nt = 0; nt < 16; nt++)
#pragma unroll
        for (int r = 0; r < 4; r++) o[nt][r] = 0.f;

    const int qrow_warp = qt * AQT + wid * 16;
    const int nkt = 2 * qt + 2;

    for (int kt = 0; kt < nkt; kt++) {
        __syncthreads();
        {
            const __nv_bfloat16* g = kh + hb + (size_t)kt * AKT * HDIM;
#pragma unroll
            for (int p = 0; p < 4; p++) {
                int i = p * 256 + tid;
                int row = i >> 4, c = i & 15;
                CP_ASYNC16(sbase + (unsigned)(SM_KHI + row * KST + c * 8) * 2u, g + row * HDIM + c * 8);
            }
            g = kl + hb + (size_t)kt * AKT * HDIM;
#pragma unroll
            for (int p = 0; p < 4; p++) {
                int i = p * 256 + tid;
                int row = i >> 4, c = i & 15;
                CP_ASYNC16(sbase + (unsigned)(SM_KLO + row * KST + c * 8) * 2u, g + row * HDIM + c * 8);
            }
            CP_COMMIT();
        }
        {
            const int kv = tid & 63;
            const int dg = tid >> 6;
            uint4 tv[4];
            const __nv_bfloat16* g = vh + hb + (size_t)(kt * AKT + kv) * HDIM + dg * 32;
#pragma unroll
            for (int c = 0; c < 4; c++) tv[c] = *(const uint4*)(g + c * 8);
            const __nv_bfloat16* tb = (const __nv_bfloat16*)tv;
#pragma unroll
            for (int j = 0; j < 32; j++)
                sma[SM_VHI + (dg * 32 + j) * VST + kv] = tb[j];
            g = vl + hb + (size_t)(kt * AKT + kv) * HDIM + dg * 32;
#pragma unroll
            for (int c = 0; c < 4; c++) tv[c] = *(const uint4*)(g + c * 8);
#pragma unroll
            for (int j = 0; j < 32; j++)
                sma[SM_VLO + (dg * 32 + j) * VST + kv] = tb[j];
        }
        CP_WAIT(0);
        __syncthreads();

        const bool active = (kt * AKT <= qrow_warp + 15);
        if (active) {
            float sreg[8][4];
#pragma unroll
            for (int nt = 0; nt < 8; nt++)
#pragma unroll
                for (int r = 0; r < 4; r++) sreg[nt][r] = 0.f;

#pragma unroll
            for (int d8 = 0; d8 < 8; d8++) {
                const int kof = d8 * 16 + 2 * qid;
                unsigned ahi[4], alo[4];
                {
                    const __nv_bfloat16* p = sma + SM_QHI + (wid * 16 + grp) * QST + kof;
                    ahi[0] = *(const unsigned*)(p);
                    ahi[1] = *(const unsigned*)(p + 8 * QST);
                    ahi[2] = *(const unsigned*)(p + 8);
                    ahi[3] = *(const unsigned*)(p + 8 * QST + 8);
                    const __nv_bfloat16* pl = sma + SM_QLO + (wid * 16 + grp) * QST + kof;
                    alo[0] = *(const unsigned*)(pl);
                    alo[1] = *(const unsigned*)(pl + 8 * QST);
                    alo[2] = *(const unsigned*)(pl + 8);
                    alo[3] = *(const unsigned*)(pl + 8 * QST + 8);
                }
#pragma unroll
                for (int nt = 0; nt < 8; nt++) {
                    unsigned bhi[2], blo[2];
                    const __nv_bfloat16* p = sma + SM_KHI + (nt * 8 + grp) * KST + kof;
                    bhi[0] = *(const unsigned*)(p);
                    bhi[1] = *(const unsigned*)(p + 8);
                    const __nv_bfloat16* pl = sma + SM_KLO + (nt * 8 + grp) * KST + kof;
                    blo[0] = *(const unsigned*)(pl);
                    blo[1] = *(const unsigned*)(pl + 8);
                    mma_bf16(sreg[nt], ahi, bhi);
                    mma_bf16(sreg[nt], ahi, blo);
                    mma_bf16(sreg[nt], alo, bhi);
                }
            }

            const int row0 = qrow_warp + grp;
            const int row1 = row0 + 8;
#pragma unroll
            for (int nt = 0; nt < 8; nt++) {
                const int c0 = kt * AKT + nt * 8 + 2 * qid;
                const int c1 = c0 + 1;
                sreg[nt][0] = (c0 <= row0) ? sreg[nt][0] * scale : -1e30f;
                sreg[nt][1] = (c1 <= row0) ? sreg[nt][1] * scale : -1e30f;
                sreg[nt][2] = (c0 <= row1) ? sreg[nt][2] * scale : -1e30f;
                sreg[nt][3] = (c1 <= row1) ? sreg[nt][3] * scale : -1e30f;
            }

            float tm0 = -1e30f, tm1 = -1e30f;
#pragma unroll
            for (int nt = 0; nt < 8; nt++) {
                tm0 = fmaxf(tm0, fmaxf(sreg[nt][0], sreg[nt][1]));
                tm1 = fmaxf(tm1, fmaxf(sreg[nt][2], sreg[nt][3]));
            }
            tm0 = fmaxf(tm0, __shfl_xor_sync(0xffffffffu, tm0, 1));
            tm0 = fmaxf(tm0, __shfl_xor_sync(0xffffffffu, tm0, 2));
            tm1 = fmaxf(tm1, __shfl_xor_sync(0xffffffffu, tm1, 1));
            tm1 = fmaxf(tm1, __shfl_xor_sync(0xffffffffu, tm1, 2));
            const float mn0 = fmaxf(m0, tm0);
            const float mn1 = fmaxf(m1, tm1);
            const float al0 = __expf(m0 - mn0);
            const float al1 = __expf(m1 - mn1);
            m0 = mn0; m1 = mn1;
            float ps0 = 0.f, ps1 = 0.f;
#pragma unroll
            for (int nt = 0; nt < 8; nt++) {
                sreg[nt][0] = __expf(sreg[nt][0] - m0);
                sreg[nt][1] = __expf(sreg[nt][1] - m0);
                sreg[nt][2] = __expf(sreg[nt][2] - m1);
                sreg[nt][3] = __expf(sreg[nt][3] - m1);
                ps0 += sreg[nt][0] + sreg[nt][1];
                ps1 += sreg[nt][2] + sreg[nt][3];
            }
            l0 = l0 * al0 + ps0;
            l1 = l1 * al1 + ps1;
#pragma unroll
            for (int nt = 0; nt < 16; nt++) {
                o[nt][0] *= al0; o[nt][1] *= al0;
                o[nt][2] *= al1; o[nt][3] *= al1;
            }

#pragma unroll
            for (int c = 0; c < 4; c++) {
                unsigned phi[4], plo[4];
#pragma unroll
                for (int half = 0; half < 2; half++) {
                    const float x0 = sreg[2 * c + half][0];
                    const float x1 = sreg[2 * c + half][1];
                    const float x2 = sreg[2 * c + half][2];
                    const float x3 = sreg[2 * c + half][3];
                    __nv_bfloat16 h0 = __float2bfloat16(x0);
                    __nv_bfloat16 h1 = __float2bfloat16(x1);
                    __nv_bfloat16 h2 = __float2bfloat16(x2);
                    __nv_bfloat16 h3 = __float2bfloat16(x3);
                    phi[0 + 2 * half] = pack_bf16x2(__bfloat162float(h0), __bfloat162float(h1));
                    phi[1 + 2 * half] = pack_bf16x2(__bfloat162float(h2), __bfloat162float(h3));
                    plo[0 + 2 * half] = pack_bf16x2(x0 - __bfloat162float(h0), x1 - __bfloat162float(h1));
                    plo[1 + 2 * half] = pack_bf16x2(x2 - __bfloat162float(h2), x3 - __bfloat162float(h3));
                }
                const int kof = 2 * qid + 16 * c;
#pragma unroll
                for (int nt = 0; nt < 16; nt++) {
                    unsigned bhi[2], blo[2];
                    const __nv_bfloat16* p = sma + SM_VHI + (nt * 8 + grp) * VST + kof;
                    bhi[0] = *(const unsigned*)(p);
                    bhi[1] = *(const unsigned*)(p + 8);
                    const __nv_bfloat16* pl = sma + SM_VLO + (nt * 8 + grp) * VST + kof;
                    blo[0] = *(const unsigned*)(pl);
                    blo[1] = *(const unsigned*)(pl + 8);
                    mma_bf16(o[nt], phi, bhi);
                    mma_bf16(o[nt], plo, bhi);
                    mma_bf16(o[nt], phi, blo);
                }
            }
        }
    }

    l0 += __shfl_xor_sync(0xffffffffu, l0, 1);
    l0 += __shfl_xor_sync(0xffffffffu, l0, 2);
    l1 += __shfl_xor_sync(0xffffffffu, l1, 1);
    l1 += __shfl_xor_sync(0xffffffffu, l1, 2);
    const float inv0 = 1.0f / l0;
    const float inv1 = 1.0f / l1;

    const int row0 = b * SLEN + qt * AQT + wid * 16 + grp;
#pragma unroll
    for (int nt = 0; nt < 16; nt++) {
        const int col = h * HDIM + nt * 8 + 2 * qid;
        float v0 = o[nt][0] * inv0, v1 = o[nt][1] * inv0;
        float v2 = o[nt][2] * inv1, v3 = o[nt][3] * inv1;
        __nv_bfloat16 h0, l0b, h1, l1b, h2, l2b, h3, l3b;
        split_bf16(v0, h0, l0b); split_bf16(v1, h1, l1b);
        split_bf16(v2, h2, l2b); split_bf16(v3, h3, l3b);
        *(__nv_bfloat162*)(ctx_hi + (size_t)row0 * HID + col) = __nv_bfloat162(h0, h1);
        *(__nv_bfloat162*)(ctx_lo + (size_t)row0 * HID + col) = __nv_bfloat162(l0b, l1b);
        *(__nv_bfloat162*)(ctx_hi + (size_t)(row0 + 8) * HID + col) = __nv_bfloat162(h2, h3);
        *(__nv_bfloat162*)(ctx_lo + (size_t)(row0 + 8) * HID + col) = __nv_bfloat162(l2b, l3b);
    }
}

// ---------------- launch ----------------
extern "C" void kernel_launch(void* const* d_in, const int* in_sizes, int n_in,
                              void* d_out, int out_size)
{
    const float* hs    = (const float*)d_in[0];
    const int*   pos   = (const int*)d_in[1];
    const float* Wqkv  = (const float*)d_in[2];
    const float* bqkv  = (const float*)d_in[3];
    const float* Wo    = (const float*)d_in[4];
    float* out = (float*)d_out;

    float *qkv;
    __nv_bfloat16 *hs_hi, *hs_lo, *ctx_hi, *ctx_lo, *wqkv_hi, *wqkv_lo, *wo_hi, *wo_lo;
    __nv_bfloat16 *q_hi, *q_lo, *k_hi, *k_lo, *v_hi, *v_lo;
    cudaGetSymbolAddress((void**)&qkv, g_qkv);
    cudaGetSymbolAddress((void**)&hs_hi, g_hs_hi);
    cudaGetSymbolAddress((void**)&hs_lo, g_hs_lo);
    cudaGetSymbolAddress((void**)&ctx_hi, g_ctx_hi);
    cudaGetSymbolAddress((void**)&ctx_lo, g_ctx_lo);
    cudaGetSymbolAddress((void**)&wqkv_hi, g_wqkv_hi);
    cudaGetSymbolAddress((void**)&wqkv_lo, g_wqkv_lo);
    cudaGetSymbolAddress((void**)&wo_hi, g_wo_hi);
    cudaGetSymbolAddress((void**)&wo_lo, g_wo_lo);
    cudaGetSymbolAddress((void**)&q_hi, g_q_hi);
    cudaGetSymbolAddress((void**)&q_lo, g_q_lo);
    cudaGetSymbolAddress((void**)&k_hi, g_k_hi);
    cudaGetSymbolAddress((void**)&k_lo, g_k_lo);
    cudaGetSymbolAddress((void**)&v_hi, g_v_hi);
    cudaGetSymbolAddress((void**)&v_lo, g_v_lo);

    static int configured = 0;
    if (!configured) {
        cudaFuncSetAttribute(gemm_bf16split_kernel,
                             cudaFuncAttributeMaxDynamicSharedMemorySize, GEMM_SMEM_BYTES);
        cudaFuncSetAttribute(flash_mma_kernel,
                             cudaFuncAttributeMaxDynamicSharedMemorySize, ATT_SMEM_BYTES);
        configured = 1;
    }

    // 0) splits + weight transposes
    {
        int n4 = MROWS * HID / 4;
        split_kernel<<<(n4 + 255) / 256, 256>>>(hs, hs_hi, hs_lo, n4);
        dim3 g1(QKV_N / 32, HID / 32);
        transpose_split_kernel<<<g1, dim3(32, 8)>>>(Wqkv, wqkv_hi, wqkv_lo, HID, QKV_N);
        dim3 g2(HID / 32, HID / 32);
        transpose_split_kernel<<<g2, dim3(32, 8)>>>(Wo, wo_hi, wo_lo, HID, HID);
    }
    // 1) qkv = hs @ W_qkv + b
    {
        dim3 grid(QKV_N / BN, MROWS / BM);   // (48, 32)
        gemm_bf16split_kernel<<<grid, 512, GEMM_SMEM_BYTES>>>(
            hs_hi, hs_lo, wqkv_hi, wqkv_lo, bqkv, qkv, MROWS, QKV_N, HID);
    }
    // 2) RoPE + split + relayout
    {
        int total = MROWS * NHEAD * 64;
        rope_split_kernel<<<(total + 255) / 256, 256>>>(qkv, pos);
    }
    // 3) flash attention -> ctx hi/lo bf16 (no separate split pass)
    {
        dim3 grid(SLEN / AQT, NHEAD, BATCH);   // (16, 32, 2)
        flash_mma_kernel<<<grid, 256, ATT_SMEM_BYTES>>>(q_hi, q_lo, k_hi, k_lo,
                                                        v_hi, v_lo, ctx_hi, ctx_lo);
    }
    // 4) out = ctx @ W_o
    {
        dim3 grid(HID / BN, MROWS / BM);     // (16, 32)
        gemm_bf16split_kernel<<<grid, 512, GEMM_SMEM_BYTES>>>(
            ctx_hi, ctx_lo, wo_hi, wo_lo, nullptr, out, MROWS, HID, HID);
    }
}

// round 10
// speedup vs baseline: 1.1178x; 1.1178x over previous
#include <cuda_runtime.h>
#include <cuda_bf16.h>
#include <math.h>

// Problem constants
#define BATCH 2
#define SLEN 2048
#define HID 4096
#define NHEAD 32
#define HDIM 128
#define MROWS (BATCH * SLEN)       // 4096
#define QKV_N (3 * HID)            // 12288

// ---------------- scratch (no allocations allowed) ----------------
__device__ float g_qkv[(size_t)MROWS * QKV_N];   // 201 MB
__device__ __nv_bfloat16 g_hs_hi[(size_t)MROWS * HID];
__device__ __nv_bfloat16 g_hs_lo[(size_t)MROWS * HID];
__device__ __nv_bfloat16 g_ctx_hi[(size_t)MROWS * HID];
__device__ __nv_bfloat16 g_ctx_lo[(size_t)MROWS * HID];
__device__ __nv_bfloat16 g_wqkv_hi[(size_t)QKV_N * HID];   // transposed [N][K]
__device__ __nv_bfloat16 g_wqkv_lo[(size_t)QKV_N * HID];
__device__ __nv_bfloat16 g_wo_hi[(size_t)HID * HID];       // transposed [N][K]
__device__ __nv_bfloat16 g_wo_lo[(size_t)HID * HID];
__device__ __nv_bfloat16 g_q_hi[(size_t)MROWS * HID];
__device__ __nv_bfloat16 g_q_lo[(size_t)MROWS * HID];
__device__ __nv_bfloat16 g_k_hi[(size_t)MROWS * HID];
__device__ __nv_bfloat16 g_k_lo[(size_t)MROWS * HID];
__device__ __nv_bfloat16 g_v_hi[(size_t)MROWS * HID];
__device__ __nv_bfloat16 g_v_lo[(size_t)MROWS * HID];

// ---------------- helpers ----------------
__device__ __forceinline__ void split_bf16(float x, __nv_bfloat16& h, __nv_bfloat16& l)
{
    h = __float2bfloat16(x);
    l = __float2bfloat16(x - __bfloat162float(h));
}

__device__ __forceinline__ unsigned pack_bf16x2(float x, float y)
{
    unsigned r;
    asm("cvt.rn.bf16x2.f32 %0, %1, %2;" : "=r"(r) : "f"(y), "f"(x));
    return r;
}

#define CP_ASYNC16(dst, src) \
    asm volatile("cp.async.cg.shared.global [%0], [%1], 16;\n" :: "r"(dst), "l"(src))
#define CP_COMMIT() asm volatile("cp.async.commit_group;\n" ::: "memory")
#define CP_WAIT(n)  asm volatile("cp.async.wait_group %0;\n" :: "n"(n) : "memory")

#define LDSM_X4(r0, r1, r2, r3, addr) \
    asm volatile("ldmatrix.sync.aligned.m8n8.x4.shared.b16 {%0,%1,%2,%3}, [%4];" \
        : "=r"(r0), "=r"(r1), "=r"(r2), "=r"(r3) : "r"(addr))

__device__ __forceinline__ void mma_bf16(float* c, const unsigned* a, const unsigned* b)
{
    asm volatile(
        "mma.sync.aligned.m16n8k16.row.col.f32.bf16.bf16.f32 "
        "{%0,%1,%2,%3},{%4,%5,%6,%7},{%8,%9},{%0,%1,%2,%3};"
        : "+f"(c[0]), "+f"(c[1]), "+f"(c[2]), "+f"(c[3])
        : "r"(a[0]), "r"(a[1]), "r"(a[2]), "r"(a[3]), "r"(b[0]), "r"(b[1]));
}

// ---------------- split / transpose kernels ----------------
__global__ void split_kernel(const float* __restrict__ src,
                             __nv_bfloat16* __restrict__ hi,
                             __nv_bfloat16* __restrict__ lo, int n4)
{
    int i = blockIdx.x * blockDim.x + threadIdx.x;
    if (i >= n4) return;
    float4 v = ((const float4*)src)[i];
    __nv_bfloat16 h0, h1, h2, h3, l0, l1, l2, l3;
    split_bf16(v.x, h0, l0); split_bf16(v.y, h1, l1);
    split_bf16(v.z, h2, l2); split_bf16(v.w, h3, l3);
    __nv_bfloat162* hp = (__nv_bfloat162*)(hi + (size_t)i * 4);
    __nv_bfloat162* lp = (__nv_bfloat162*)(lo + (size_t)i * 4);
    hp[0] = __nv_bfloat162(h0, h1); hp[1] = __nv_bfloat162(h2, h3);
    lp[0] = __nv_bfloat162(l0, l1); lp[1] = __nv_bfloat162(l2, l3);
}

__global__ void transpose_split_kernel(const float* __restrict__ W,
                                       __nv_bfloat16* __restrict__ hi,
                                       __nv_bfloat16* __restrict__ lo,
                                       int K, int N)
{
    __shared__ float t[32][33];
    const int n0 = blockIdx.x * 32;
    const int k0 = blockIdx.y * 32;
    const int tx = threadIdx.x;
    const int ty = threadIdx.y;
#pragma unroll
    for (int j = 0; j < 32; j += 8)
        t[ty + j][tx] = W[(size_t)(k0 + ty + j) * N + n0 + tx];
    __syncthreads();
#pragma unroll
    for (int j = 0; j < 32; j += 8) {
        float x = t[tx][ty + j];
        __nv_bfloat16 h, l;
        split_bf16(x, h, l);
        size_t o = (size_t)(n0 + ty + j) * K + k0 + tx;
        hi[o] = h;
        lo[o] = l;
    }
}

// ===== bf16-split tensor-core GEMM (128x128, 2-stage, single barrier/iter) =====
#define BM 128
#define BN 128
#define BK 32
#define SSTRIDE 40                       // 80B pitch: 16B-aligned, conflict-free
#define TILE_ELEMS (128 * SSTRIDE)       // 5120
#define OFF_BHI (2 * TILE_ELEMS)
#define STAGE_ELEMS (4 * TILE_ELEMS)     // 20480
#define NSTAGE 2
#define GEMM_SMEM_BYTES (NSTAGE * STAGE_ELEMS * 2)   // 81920 per CTA (2 CTA/SM)

__global__ __launch_bounds__(256)
void gemm_bf16split_kernel(const __nv_bfloat16* __restrict__ Ahi,
                           const __nv_bfloat16* __restrict__ Alo,
                           const __nv_bfloat16* __restrict__ Bhi,
                           const __nv_bfloat16* __restrict__ Blo,
                           const float* __restrict__ bias, float* __restrict__ C,
                           int M, int N, int K)
{
    extern __shared__ __nv_bfloat16 sm[];
    const int tid = threadIdx.x;
    const int wid = tid >> 5;
    const int lane = tid & 31;
    const int grp = lane >> 2;
    const int qid = lane & 3;
    const int warp_m = wid >> 2;   // 0..1 (64 rows)
    const int warp_n = wid & 3;    // 0..3 (32 cols)

    const int m0 = blockIdx.y * BM;
    const int n0 = blockIdx.x * BN;

    float acc[4][4][4];
#pragma unroll
    for (int i = 0; i < 4; i++)
#pragma unroll
        for (int j = 0; j < 4; j++)
#pragma unroll
            for (int r = 0; r < 4; r++) acc[i][j][r] = 0.f;

    unsigned smem_base = (unsigned)__cvta_generic_to_shared(sm);
    const int NIT = K / BK;

    // ldmatrix per-lane element offsets
    const unsigned a_elem = (unsigned)((warp_m * 64 + (lane & 15)) * SSTRIDE
                                       + ((lane >> 4) & 1) * 8);
    const unsigned b_elem = (unsigned)((warp_n * 32 + ((lane >> 4) & 1) * 8 + (lane & 7)) * SSTRIDE
                                       + ((lane >> 3) & 1) * 8);

    auto load_stage = [&](int st, int k0) {
        unsigned sb = smem_base + (unsigned)(st * STAGE_ELEMS) * 2u;
        const __nv_bfloat16* gsrc[4] = {Ahi, Alo, Bhi, Blo};
        const int gm0[4] = {m0, m0, n0, n0};
#pragma unroll
        for (int arr = 0; arr < 4; arr++) {
            unsigned sa = sb + (unsigned)(arr * TILE_ELEMS) * 2u;
            const __nv_bfloat16* g = gsrc[arr];
#pragma unroll
            for (int p = 0; p < 2; p++) {
                int i = p * 256 + tid;
                int row = i >> 2;
                int c = i & 3;
                CP_ASYNC16(sa + (unsigned)(row * SSTRIDE + c * 8) * 2u,
                           g + (size_t)(gm0[arr] + row) * K + k0 + c * 8);
            }
        }
    };

    load_stage(0, 0);
    CP_COMMIT();

    int st = 0;
    for (int it = 0; it < NIT; it++) {
        CP_WAIT(0);
        __syncthreads();    // stage st loaded everywhere; all warps done with
                            // stage st^1 from iter it-1 -> safe to refill it.
        if (it + 1 < NIT) {
            load_stage(st ^ 1, (it + 1) * BK);
            CP_COMMIT();
        }

        const unsigned stg = smem_base + (unsigned)(st * STAGE_ELEMS) * 2u;
        const unsigned lo_off = (unsigned)TILE_ELEMS * 2u;
        const unsigned b_base = stg + (unsigned)OFF_BHI * 2u;

#pragma unroll
        for (int kk = 0; kk < 2; kk++) {
            unsigned ahi[4][4], alo[4][4], bh[2][4], bl[2][4];
#pragma unroll
            for (int mt = 0; mt < 4; mt++) {
                unsigned ad = stg + (a_elem + (unsigned)(mt * 16 * SSTRIDE + kk * 16)) * 2u;
                LDSM_X4(ahi[mt][0], ahi[mt][1], ahi[mt][2], ahi[mt][3], ad);
                LDSM_X4(alo[mt][0], alo[mt][1], alo[mt][2], alo[mt][3], ad + lo_off);
            }
#pragma unroll
            for (int p = 0; p < 2; p++) {
                unsigned bd = b_base + (b_elem + (unsigned)(p * 16 * SSTRIDE + kk * 16)) * 2u;
                LDSM_X4(bh[p][0], bh[p][1], bh[p][2], bh[p][3], bd);
                LDSM_X4(bl[p][0], bl[p][1], bl[p][2], bl[p][3], bd + lo_off);
            }
            // hi * hi
#pragma unroll
            for (int mt = 0; mt < 4; mt++)
#pragma unroll
                for (int p = 0; p < 2; p++) {
                    mma_bf16(acc[mt][2 * p + 0], ahi[mt], &bh[p][0]);
                    mma_bf16(acc[mt][2 * p + 1], ahi[mt], &bh[p][2]);
                }
            // hi * lo
#pragma unroll
            for (int mt = 0; mt < 4; mt++)
#pragma unroll
                for (int p = 0; p < 2; p++) {
                    mma_bf16(acc[mt][2 * p + 0], ahi[mt], &bl[p][0]);
                    mma_bf16(acc[mt][2 * p + 1], ahi[mt], &bl[p][2]);
                }
            // lo * hi
#pragma unroll
            for (int mt = 0; mt < 4; mt++)
#pragma unroll
                for (int p = 0; p < 2; p++) {
                    mma_bf16(acc[mt][2 * p + 0], alo[mt], &bh[p][0]);
                    mma_bf16(acc[mt][2 * p + 1], alo[mt], &bh[p][2]);
                }
        }
        st ^= 1;
    }

#pragma unroll
    for (int mt = 0; mt < 4; mt++) {
        const int mrow = m0 + warp_m * 64 + mt * 16 + grp;
#pragma unroll
        for (int nt = 0; nt < 4; nt++) {
            const int col = n0 + warp_n * 32 + nt * 8 + 2 * qid;
            float b0 = bias ? bias[col] : 0.f;
            float b1 = bias ? bias[col + 1] : 0.f;
            float2 v0 = make_float2(acc[mt][nt][0] + b0, acc[mt][nt][1] + b1);
            float2 v1 = make_float2(acc[mt][nt][2] + b0, acc[mt][nt][3] + b1);
            *(float2*)(C + (size_t)mrow * N + col) = v0;
            *(float2*)(C + (size_t)(mrow + 8) * N + col) = v1;
        }
    }
}

// ---------------- fused RoPE + split + relayout ----------------
__global__ void rope_split_kernel(const float* __restrict__ qkv,
                                  const int* __restrict__ positions)
{
    int idx = blockIdx.x * blockDim.x + threadIdx.x;
    if (idx >= MROWS * NHEAD * 64) return;
    const int i = idx & 63;
    const int h = (idx >> 6) & 31;
    const int m = idx >> 11;
    const int b = m >> 11;
    const int s = m & 2047;

    const float pos = (float)positions[m];
    const float inv_freq = powf(10000.0f, -(float)i / 64.0f);
    const float ang = pos * inv_freq;
    const float c = cosf(ang);
    const float sn = sinf(ang);

    const float* row = qkv + (size_t)m * QKV_N + h * HDIM;
    const size_t hb = ((size_t)((b * NHEAD + h) * SLEN) + s) * HDIM;

    {
        float x1 = row[i], x2 = row[i + 64];
        float y1 = x1 * c - x2 * sn;
        float y2 = x2 * c + x1 * sn;
        __nv_bfloat16 h1, l1, h2, l2;
        split_bf16(y1, h1, l1); split_bf16(y2, h2, l2);
        g_q_hi[hb + i] = h1; g_q_hi[hb + i + 64] = h2;
        g_q_lo[hb + i] = l1; g_q_lo[hb + i + 64] = l2;
    }
    {
        float x1 = row[HID + i], x2 = row[HID + i + 64];
        float y1 = x1 * c - x2 * sn;
        float y2 = x2 * c + x1 * sn;
        __nv_bfloat16 h1, l1, h2, l2;
        split_bf16(y1, h1, l1); split_bf16(y2, h2, l2);
        g_k_hi[hb + i] = h1; g_k_hi[hb + i + 64] = h2;
        g_k_lo[hb + i] = l1; g_k_lo[hb + i + 64] = l2;
    }
    {
        float x1 = row[2 * HID + i], x2 = row[2 * HID + i + 64];
        __nv_bfloat16 h1, l1, h2, l2;
        split_bf16(x1, h1, l1); split_bf16(x2, h2, l2);
        g_v_hi[hb + i] = h1; g_v_hi[hb + i + 64] = h2;
        g_v_lo[hb + i] = l1; g_v_lo[hb + i + 64] = l2;
    }
}

// ---------------- tensor-core flash attention (bf16-split, causal) ----------------
#define AQT 128
#define AKT 64
#define QST 136
#define KST 136
#define VST 72
#define SM_QHI 0
#define SM_QLO (SM_QHI + AQT * QST)
#define SM_KHI (SM_QLO + AQT * QST)
#define SM_KLO (SM_KHI + AKT * KST)
#define SM_VHI (SM_KLO + AKT * KST)
#define SM_VLO (SM_VHI + AQT * VST)
#define ATT_SMEM_ELEMS (SM_VLO + AQT * VST)
#define ATT_SMEM_BYTES (ATT_SMEM_ELEMS * 2)   // 141312

__global__ __launch_bounds__(256)
void flash_mma_kernel(const __nv_bfloat16* __restrict__ qh, const __nv_bfloat16* __restrict__ ql,
                      const __nv_bfloat16* __restrict__ kh, const __nv_bfloat16* __restrict__ kl,
                      const __nv_bfloat16* __restrict__ vh, const __nv_bfloat16* __restrict__ vl,
                      __nv_bfloat16* __restrict__ ctx_hi, __nv_bfloat16* __restrict__ ctx_lo)
{
    extern __shared__ __nv_bfloat16 sma[];
    const int qt = blockIdx.x;
    const int h  = blockIdx.y;
    const int b  = blockIdx.z;
    const int tid = threadIdx.x;
    const int wid = tid >> 5;
    const int lane = tid & 31;
    const int grp = lane >> 2;
    const int qid = lane & 3;
    const size_t hb = ((size_t)(b * NHEAD + h)) * SLEN * HDIM;
    unsigned sbase = (unsigned)__cvta_generic_to_shared(sma);
    const float scale = 0.08838834764831845f;

    {
        const __nv_bfloat16* g = qh + hb + (size_t)qt * AQT * HDIM;
#pragma unroll
        for (int p = 0; p < 8; p++) {
            int i = p * 256 + tid;
            int row = i >> 4, c = i & 15;
            CP_ASYNC16(sbase + (unsigned)(SM_QHI + row * QST + c * 8) * 2u, g + row * HDIM + c * 8);
        }
        g = ql + hb + (size_t)qt * AQT * HDIM;
#pragma unroll
        for (int p = 0; p < 8; p++) {
            int i = p * 256 + tid;
            int row = i >> 4, c = i & 15;
            CP_ASYNC16(sbase + (unsigned)(SM_QLO + row * QST + c * 8) * 2u, g + row * HDIM + c * 8);
        }
        CP_COMMIT();
    }

    float m0 = -1e30f, m1 = -1e30f, l0 = 0.f, l1 = 0.f;
    float o[16][4];
#pragma unroll
    for (int nt = 0; nt < 16; nt++)
#pragma unroll
        for (int r = 0; r < 4; r++) o[nt][r] = 0.f;

    const int qrow_warp = qt * AQT + wid * 16;
    const int nkt = 2 * qt + 2;

    for (int kt = 0; kt < nkt; kt++) {
        __syncthreads();
        {
            const __nv_bfloat16* g = kh + hb + (size_t)kt * AKT * HDIM;
#pragma unroll
            for (int p = 0; p < 4; p++) {
                int i = p * 256 + tid;
                int row = i >> 4, c = i & 15;
                CP_ASYNC16(sbase + (unsigned)(SM_KHI + row * KST + c * 8) * 2u, g + row * HDIM + c * 8);
            }
            g = kl + hb + (size_t)kt * AKT * HDIM;
#pragma unroll
            for (int p = 0; p < 4; p++) {
                int i = p * 256 + tid;
                int row = i >> 4, c = i & 15;
                CP_ASYNC16(sbase + (unsigned)(SM_KLO + row * KST + c * 8) * 2u, g + row * HDIM + c * 8);
            }
            CP_COMMIT();
        }
        {
            const int kv = tid & 63;
            const int dg = tid >> 6;
            uint4 tv[4];
            const __nv_bfloat16* g = vh + hb + (size_t)(kt * AKT + kv) * HDIM + dg * 32;
#pragma unroll
            for (int c = 0; c < 4; c++) tv[c] = *(const uint4*)(g + c * 8);
            const __nv_bfloat16* tb = (const __nv_bfloat16*)tv;
#pragma unroll
            for (int j = 0; j < 32; j++)
                sma[SM_VHI + (dg * 32 + j) * VST + kv] = tb[j];
            g = vl + hb + (size_t)(kt * AKT + kv) * HDIM + dg * 32;
#pragma unroll
            for (int c = 0; c < 4; c++) tv[c] = *(const uint4*)(g + c * 8);
#pragma unroll
            for (int j = 0; j < 32; j++)
                sma[SM_VLO + (dg * 32 + j) * VST + kv] = tb[j];
        }
        CP_WAIT(0);
        __syncthreads();

        const bool active = (kt * AKT <= qrow_warp + 15);
        if (active) {
            float sreg[8][4];
#pragma unroll
            for (int nt = 0; nt < 8; nt++)
#pragma unroll
                for (int r = 0; r < 4; r++) sreg[nt][r] = 0.f;

#pragma unroll
            for (int d8 = 0; d8 < 8; d8++) {
                const int kof = d8 * 16 + 2 * qid;
                unsigned ahi[4], alo[4];
                {
                    const __nv_bfloat16* p = sma + SM_QHI + (wid * 16 + grp) * QST + kof;
                    ahi[0] = *(const unsigned*)(p);
                    ahi[1] = *(const unsigned*)(p + 8 * QST);
                    ahi[2] = *(const unsigned*)(p + 8);
                    ahi[3] = *(const unsigned*)(p + 8 * QST + 8);
                    const __nv_bfloat16* pl = sma + SM_QLO + (wid * 16 + grp) * QST + kof;
                    alo[0] = *(const unsigned*)(pl);
                    alo[1] = *(const unsigned*)(pl + 8 * QST);
                    alo[2] = *(const unsigned*)(pl + 8);
                    alo[3] = *(const unsigned*)(pl + 8 * QST + 8);
                }
#pragma unroll
                for (int nt = 0; nt < 8; nt++) {
                    unsigned bhi[2], blo[2];
                    const __nv_bfloat16* p = sma + SM_KHI + (nt * 8 + grp) * KST + kof;
                    bhi[0] = *(const unsigned*)(p);
                    bhi[1] = *(const unsigned*)(p + 8);
                    const __nv_bfloat16* pl = sma + SM_KLO + (nt * 8 + grp) * KST + kof;
                    blo[0] = *(const unsigned*)(pl);
                    blo[1] = *(const unsigned*)(pl + 8);
                    mma_bf16(sreg[nt], ahi, bhi);
                    mma_bf16(sreg[nt], ahi, blo);
                    mma_bf16(sreg[nt], alo, bhi);
                }
            }

            const int row0 = qrow_warp + grp;
            const int row1 = row0 + 8;
#pragma unroll
            for (int nt = 0; nt < 8; nt++) {
                const int c0 = kt * AKT + nt * 8 + 2 * qid;
                const int c1 = c0 + 1;
                sreg[nt][0] = (c0 <= row0) ? sreg[nt][0] * scale : -1e30f;
                sreg[nt][1] = (c1 <= row0) ? sreg[nt][1] * scale : -1e30f;
                sreg[nt][2] = (c0 <= row1) ? sreg[nt][2] * scale : -1e30f;
                sreg[nt][3] = (c1 <= row1) ? sreg[nt][3] * scale : -1e30f;
            }

            float tm0 = -1e30f, tm1 = -1e30f;
#pragma unroll
            for (int nt = 0; nt < 8; nt++) {
                tm0 = fmaxf(tm0, fmaxf(sreg[nt][0], sreg[nt][1]));
                tm1 = fmaxf(tm1, fmaxf(sreg[nt][2], sreg[nt][3]));
            }
            tm0 = fmaxf(tm0, __shfl_xor_sync(0xffffffffu, tm0, 1));
            tm0 = fmaxf(tm0, __shfl_xor_sync(0xffffffffu, tm0, 2));
            tm1 = fmaxf(tm1, __shfl_xor_sync(0xffffffffu, tm1, 1));
            tm1 = fmaxf(tm1, __shfl_xor_sync(0xffffffffu, tm1, 2));
            const float mn0 = fmaxf(m0, tm0);
            const float mn1 = fmaxf(m1, tm1);
            const float al0 = __expf(m0 - mn0);
            const float al1 = __expf(m1 - mn1);
            m0 = mn0; m1 = mn1;
            float ps0 = 0.f, ps1 = 0.f;
#pragma unroll
            for (int nt = 0; nt < 8; nt++) {
                sreg[nt][0] = __expf(sreg[nt][0] - m0);
                sreg[nt][1] = __expf(sreg[nt][1] - m0);
                sreg[nt][2] = __expf(sreg[nt][2] - m1);
                sreg[nt][3] = __expf(sreg[nt][3] - m1);
                ps0 += sreg[nt][0] + sreg[nt][1];
                ps1 += sreg[nt][2] + sreg[nt][3];
            }
            l0 = l0 * al0 + ps0;
            l1 = l1 * al1 + ps1;
#pragma unroll
            for (int nt = 0; nt < 16; nt++) {
                o[nt][0] *= al0; o[nt][1] *= al0;
                o[nt][2] *= al1; o[nt][3] *= al1;
            }

#pragma unroll
            for (int c = 0; c < 4; c++) {
                unsigned phi[4], plo[4];
#pragma unroll
                for (int half = 0; half < 2; half++) {
                    const float x0 = sreg[2 * c + half][0];
                    const float x1 = sreg[2 * c + half][1];
                    const float x2 = sreg[2 * c + half][2];
                    const float x3 = sreg[2 * c + half][3];
                    __nv_bfloat16 h0 = __float2bfloat16(x0);
                    __nv_bfloat16 h1 = __float2bfloat16(x1);
                    __nv_bfloat16 h2 = __float2bfloat16(x2);
                    __nv_bfloat16 h3 = __float2bfloat16(x3);
                    phi[0 + 2 * half] = pack_bf16x2(__bfloat162float(h0), __bfloat162float(h1));
                    phi[1 + 2 * half] = pack_bf16x2(__bfloat162float(h2), __bfloat162float(h3));
                    plo[0 + 2 * half] = pack_bf16x2(x0 - __bfloat162float(h0), x1 - __bfloat162float(h1));
                    plo[1 + 2 * half] = pack_bf16x2(x2 - __bfloat162float(h2), x3 - __bfloat162float(h3));
                }
                const int kof = 2 * qid + 16 * c;
#pragma unroll
                for (int nt = 0; nt < 16; nt++) {
                    unsigned bhi[2], blo[2];
                    const __nv_bfloat16* p = sma + SM_VHI + (nt * 8 + grp) * VST + kof;
                    bhi[0] = *(const unsigned*)(p);
                    bhi[1] = *(const unsigned*)(p + 8);
                    const __nv_bfloat16* pl = sma + SM_VLO + (nt * 8 + grp) * VST + kof;
                    blo[0] = *(const unsigned*)(pl);
                    blo[1] = *(const unsigned*)(pl + 8);
                    mma_bf16(o[nt], phi, bhi);
                    mma_bf16(o[nt], plo, bhi);
                    mma_bf16(o[nt], phi, blo);
                }
            }
        }
    }

    l0 += __shfl_xor_sync(0xffffffffu, l0, 1);
    l0 += __shfl_xor_sync(0xffffffffu, l0, 2);
    l1 += __shfl_xor_sync(0xffffffffu, l1, 1);
    l1 += __shfl_xor_sync(0xffffffffu, l1, 2);
    const float inv0 = 1.0f / l0;
    const float inv1 = 1.0f / l1;

    const int row0 = b * SLEN + qt * AQT + wid * 16 + grp;
#pragma unroll
    for (int nt = 0; nt < 16; nt++) {
        const int col = h * HDIM + nt * 8 + 2 * qid;
        float v0 = o[nt][0] * inv0, v1 = o[nt][1] * inv0;
        float v2 = o[nt][2] * inv1, v3 = o[nt][3] * inv1;
        __nv_bfloat16 h0, l0b, h1, l1b, h2, l2b, h3, l3b;
        split_bf16(v0, h0, l0b); split_bf16(v1, h1, l1b);
        split_bf16(v2, h2, l2b); split_bf16(v3, h3, l3b);
        *(__nv_bfloat162*)(ctx_hi + (size_t)row0 * HID + col) = __nv_bfloat162(h0, h1);
        *(__nv_bfloat162*)(ctx_lo + (size_t)row0 * HID + col) = __nv_bfloat162(l0b, l1b);
        *(__nv_bfloat162*)(ctx_hi + (size_t)(row0 + 8) * HID + col) = __nv_bfloat162(h2, h3);
        *(__nv_bfloat162*)(ctx_lo + (size_t)(row0 + 8) * HID + col) = __nv_bfloat162(l2b, l3b);
    }
}

// ---------------- launch ----------------
extern "C" void kernel_launch(void* const* d_in, const int* in_sizes, int n_in,
                              void* d_out, int out_size)
{
    const float* hs    = (const float*)d_in[0];
    const int*   pos   = (const int*)d_in[1];
    const float* Wqkv  = (const float*)d_in[2];
    const float* bqkv  = (const float*)d_in[3];
    const float* Wo    = (const float*)d_in[4];
    float* out = (float*)d_out;

    float *qkv;
    __nv_bfloat16 *hs_hi, *hs_lo, *ctx_hi, *ctx_lo, *wqkv_hi, *wqkv_lo, *wo_hi, *wo_lo;
    __nv_bfloat16 *q_hi, *q_lo, *k_hi, *k_lo, *v_hi, *v_lo;
    cudaGetSymbolAddress((void**)&qkv, g_qkv);
    cudaGetSymbolAddress((void**)&hs_hi, g_hs_hi);
    cudaGetSymbolAddress((void**)&hs_lo, g_hs_lo);
    cudaGetSymbolAddress((void**)&ctx_hi, g_ctx_hi);
    cudaGetSymbolAddress((void**)&ctx_lo, g_ctx_lo);
    cudaGetSymbolAddress((void**)&wqkv_hi, g_wqkv_hi);
    cudaGetSymbolAddress((void**)&wqkv_lo, g_wqkv_lo);
    cudaGetSymbolAddress((void**)&wo_hi, g_wo_hi);
    cudaGetSymbolAddress((void**)&wo_lo, g_wo_lo);
    cudaGetSymbolAddress((void**)&q_hi, g_q_hi);
    cudaGetSymbolAddress((void**)&q_lo, g_q_lo);
    cudaGetSymbolAddress((void**)&k_hi, g_k_hi);
    cudaGetSymbolAddress((void**)&k_lo, g_k_lo);
    cudaGetSymbolAddress((void**)&v_hi, g_v_hi);
    cudaGetSymbolAddress((void**)&v_lo, g_v_lo);

    static int configured = 0;
    if (!configured) {
        cudaFuncSetAttribute(gemm_bf16split_kernel,
                             cudaFuncAttributeMaxDynamicSharedMemorySize, GEMM_SMEM_BYTES);
        cudaFuncSetAttribute(flash_mma_kernel,
                             cudaFuncAttributeMaxDynamicSharedMemorySize, ATT_SMEM_BYTES);
        configured = 1;
    }

    // 0) splits + weight transposes
    {
        int n4 = MROWS * HID / 4;
        split_kernel<<<(n4 + 255) / 256, 256>>>(hs, hs_hi, hs_lo, n4);
        dim3 g1(QKV_N / 32, HID / 32);
        transpose_split_kernel<<<g1, dim3(32, 8)>>>(Wqkv, wqkv_hi, wqkv_lo, HID, QKV_N);
        dim3 g2(HID / 32, HID / 32);
        transpose_split_kernel<<<g2, dim3(32, 8)>>>(Wo, wo_hi, wo_lo, HID, HID);
    }
    // 1) qkv = hs @ W_qkv + b
    {
        dim3 grid(QKV_N / BN, MROWS / BM);   // (96, 32)
        gemm_bf16split_kernel<<<grid, 256, GEMM_SMEM_BYTES>>>(
            hs_hi, hs_lo, wqkv_hi, wqkv_lo, bqkv, qkv, MROWS, QKV_N, HID);
    }
    // 2) RoPE + split + relayout
    {
        int total = MROWS * NHEAD * 64;
        rope_split_kernel<<<(total + 255) / 256, 256>>>(qkv, pos);
    }
    // 3) flash attention -> ctx hi/lo bf16 (no separate split pass)
    {
        dim3 grid(SLEN / AQT, NHEAD, BATCH);   // (16, 32, 2)
        flash_mma_kernel<<<grid, 256, ATT_SMEM_BYTES>>>(q_hi, q_lo, k_hi, k_lo,
                                                        v_hi, v_lo, ctx_hi, ctx_lo);
    }
    // 4) out = ctx @ W_o
    {
        dim3 grid(HID / BN, MROWS / BM);     // (32, 32)
        gemm_bf16split_kernel<<<grid, 256, GEMM_SMEM_BYTES>>>(
            ctx_hi, ctx_lo, wo_hi, wo_lo, nullptr, out, MROWS, HID, HID);
    }
}

// round 11
// speedup vs baseline: 1.2474x; 1.1160x over previous
#include <cuda_runtime.h>
#include <cuda_bf16.h>
#include <math.h>

// Problem constants
#define BATCH 2
#define SLEN 2048
#define HID 4096
#define NHEAD 32
#define HDIM 128
#define MROWS (BATCH * SLEN)       // 4096
#define QKV_N (3 * HID)            // 12288

// ---------------- scratch (no allocations allowed) ----------------
__device__ float g_qkv[(size_t)MROWS * QKV_N];   // 201 MB
__device__ __nv_bfloat16 g_hs_hi[(size_t)MROWS * HID];
__device__ __nv_bfloat16 g_hs_lo[(size_t)MROWS * HID];
__device__ __nv_bfloat16 g_ctx_hi[(size_t)MROWS * HID];
__device__ __nv_bfloat16 g_ctx_lo[(size_t)MROWS * HID];
__device__ __nv_bfloat16 g_wqkv_hi[(size_t)QKV_N * HID];   // transposed [N][K]
__device__ __nv_bfloat16 g_wqkv_lo[(size_t)QKV_N * HID];
__device__ __nv_bfloat16 g_wo_hi[(size_t)HID * HID];       // transposed [N][K]
__device__ __nv_bfloat16 g_wo_lo[(size_t)HID * HID];
__device__ __nv_bfloat16 g_q_hi[(size_t)MROWS * HID];
__device__ __nv_bfloat16 g_q_lo[(size_t)MROWS * HID];
__device__ __nv_bfloat16 g_k_hi[(size_t)MROWS * HID];
__device__ __nv_bfloat16 g_k_lo[(size_t)MROWS * HID];
__device__ __nv_bfloat16 g_v_hi[(size_t)MROWS * HID];
__device__ __nv_bfloat16 g_v_lo[(size_t)MROWS * HID];

// ---------------- helpers ----------------
__device__ __forceinline__ void split_bf16(float x, __nv_bfloat16& h, __nv_bfloat16& l)
{
    h = __float2bfloat16(x);
    l = __float2bfloat16(x - __bfloat162float(h));
}

__device__ __forceinline__ unsigned pack_bf16x2(float x, float y)
{
    unsigned r;
    asm("cvt.rn.bf16x2.f32 %0, %1, %2;" : "=r"(r) : "f"(y), "f"(x));
    return r;
}

#define CP_ASYNC16(dst, src) \
    asm volatile("cp.async.cg.shared.global [%0], [%1], 16;\n" :: "r"(dst), "l"(src))
#define CP_COMMIT() asm volatile("cp.async.commit_group;\n" ::: "memory")
#define CP_WAIT(n)  asm volatile("cp.async.wait_group %0;\n" :: "n"(n) : "memory")

#define LDSM_X4(r0, r1, r2, r3, addr) \
    asm volatile("ldmatrix.sync.aligned.m8n8.x4.shared.b16 {%0,%1,%2,%3}, [%4];" \
        : "=r"(r0), "=r"(r1), "=r"(r2), "=r"(r3) : "r"(addr))

__device__ __forceinline__ void mma_bf16(float* c, const unsigned* a, const unsigned* b)
{
    asm volatile(
        "mma.sync.aligned.m16n8k16.row.col.f32.bf16.bf16.f32 "
        "{%0,%1,%2,%3},{%4,%5,%6,%7},{%8,%9},{%0,%1,%2,%3};"
        : "+f"(c[0]), "+f"(c[1]), "+f"(c[2]), "+f"(c[3])
        : "r"(a[0]), "r"(a[1]), "r"(a[2]), "r"(a[3]), "r"(b[0]), "r"(b[1]));
}

// ---------------- split / transpose kernels ----------------
__global__ void split_kernel(const float* __restrict__ src,
                             __nv_bfloat16* __restrict__ hi,
                             __nv_bfloat16* __restrict__ lo, int n4)
{
    int i = blockIdx.x * blockDim.x + threadIdx.x;
    if (i >= n4) return;
    float4 v = ((const float4*)src)[i];
    __nv_bfloat16 h0, h1, h2, h3, l0, l1, l2, l3;
    split_bf16(v.x, h0, l0); split_bf16(v.y, h1, l1);
    split_bf16(v.z, h2, l2); split_bf16(v.w, h3, l3);
    __nv_bfloat162* hp = (__nv_bfloat162*)(hi + (size_t)i * 4);
    __nv_bfloat162* lp = (__nv_bfloat162*)(lo + (size_t)i * 4);
    hp[0] = __nv_bfloat162(h0, h1); hp[1] = __nv_bfloat162(h2, h3);
    lp[0] = __nv_bfloat162(l0, l1); lp[1] = __nv_bfloat162(l2, l3);
}

__global__ void transpose_split_kernel(const float* __restrict__ W,
                                       __nv_bfloat16* __restrict__ hi,
                                       __nv_bfloat16* __restrict__ lo,
                                       int K, int N)
{
    __shared__ float t[32][33];
    const int n0 = blockIdx.x * 32;
    const int k0 = blockIdx.y * 32;
    const int tx = threadIdx.x;
    const int ty = threadIdx.y;
#pragma unroll
    for (int j = 0; j < 32; j += 8)
        t[ty + j][tx] = W[(size_t)(k0 + ty + j) * N + n0 + tx];
    __syncthreads();
#pragma unroll
    for (int j = 0; j < 32; j += 8) {
        float x = t[tx][ty + j];
        __nv_bfloat16 h, l;
        split_bf16(x, h, l);
        size_t o = (size_t)(n0 + ty + j) * K + k0 + tx;
        hi[o] = h;
        lo[o] = l;
    }
}

// ===== bf16-split GEMM: 128x128, XOR-swizzled smem, 3-stage, 1 barrier/iter =====
// smem row = 32 bf16 = 64B = 4 chunks of 16B; chunk swizzle: c ^= (row>>1)&3.
#define BM 128
#define BN 128
#define BK 32
#define A_TILE_BYTES 8192                // 128 rows x 64B
#define OFF_ALO 8192
#define OFF_BHI 16384
#define OFF_BLO 24576
#define STAGE_BYTES 32768
#define NSTAGE 3
#define GEMM_SMEM_BYTES (NSTAGE * STAGE_BYTES)   // 98304 per CTA (2 CTA/SM)

__global__ __launch_bounds__(256)
void gemm_bf16split_kernel(const __nv_bfloat16* __restrict__ Ahi,
                           const __nv_bfloat16* __restrict__ Alo,
                           const __nv_bfloat16* __restrict__ Bhi,
                           const __nv_bfloat16* __restrict__ Blo,
                           const float* __restrict__ bias, float* __restrict__ C,
                           int M, int N, int K)
{
    extern __shared__ __nv_bfloat16 sm[];
    const int tid = threadIdx.x;
    const int wid = tid >> 5;
    const int lane = tid & 31;
    const int grp = lane >> 2;
    const int qid = lane & 3;
    const int warp_m = wid >> 2;   // 0..1 (64 rows)
    const int warp_n = wid & 3;    // 0..3 (32 cols)

    const int m0 = blockIdx.y * BM;
    const int n0 = blockIdx.x * BN;

    float acc[4][4][4];
#pragma unroll
    for (int i = 0; i < 4; i++)
#pragma unroll
        for (int j = 0; j < 4; j++)
#pragma unroll
            for (int r = 0; r < 4; r++) acc[i][j][r] = 0.f;

    unsigned smem_base = (unsigned)__cvta_generic_to_shared(sm);
    const int NIT = K / BK;

    // lane-constant swizzle selectors (row-dependent bits reduce to lane bits)
    const unsigned asw = ((unsigned)(lane & 15) >> 1) & 3;
    const unsigned bsw = ((unsigned)(lane & 7) >> 1) & 3;
    const unsigned a_row_byte = (unsigned)(warp_m * 64 + (lane & 15)) * 64u;
    const unsigned a_c0 = ((unsigned)lane >> 4) & 1;
    const unsigned b_row_byte = (unsigned)(warp_n * 32 + ((lane >> 4) & 1) * 8 + (lane & 7)) * 64u;
    const unsigned b_c0 = ((unsigned)lane >> 3) & 1;

    // loader coords: thread i -> row=i>>2 (0..127), chunk c=i&3
    auto load_stage = [&](int st, int k0) {
        unsigned sb = smem_base + (unsigned)(st * STAGE_BYTES);
        const __nv_bfloat16* gsrc[4] = {Ahi, Alo, Bhi, Blo};
        const int gm0[4] = {m0, m0, n0, n0};
#pragma unroll
        for (int arr = 0; arr < 4; arr++) {
            unsigned sa = sb + (unsigned)(arr * A_TILE_BYTES);
            const __nv_bfloat16* g = gsrc[arr];
#pragma unroll
            for (int p = 0; p < 2; p++) {
                int i = p * 256 + tid;
                unsigned row = (unsigned)(i >> 2);
                unsigned c = (unsigned)(i & 3);
                unsigned dst = sa + row * 64u + ((c ^ ((row >> 1) & 3)) << 4);
                CP_ASYNC16(dst, g + (size_t)(gm0[arr] + (int)row) * K + k0 + (int)c * 8);
            }
        }
    };

    load_stage(0, 0);
    CP_COMMIT();
    load_stage(1, BK);
    CP_COMMIT();

    int st = 0;
    for (int it = 0; it < NIT; it++) {
        if (it + 1 < NIT) { CP_WAIT(1); } else { CP_WAIT(0); }
        __syncthreads();    // stage st complete everywhere; all warps finished
                            // iter it-1 -> stage (st+2)%3 free to refill.
        if (it + 2 < NIT) {
            int s2 = st + 2; if (s2 >= NSTAGE) s2 -= NSTAGE;
            load_stage(s2, (it + 2) * BK);
            CP_COMMIT();
        }

        const unsigned stg = smem_base + (unsigned)(st * STAGE_BYTES);

#pragma unroll
        for (int kk = 0; kk < 2; kk++) {
            unsigned ahi[4][4], alo[4][4], bh[2][4], bl[2][4];
            const unsigned ach = (((unsigned)(kk * 2) + a_c0) ^ asw) << 4;
            const unsigned bch = (((unsigned)(kk * 2) + b_c0) ^ bsw) << 4;
#pragma unroll
            for (int mt = 0; mt < 4; mt++) {
                unsigned ad = stg + a_row_byte + (unsigned)(mt * 1024) + ach;
                LDSM_X4(ahi[mt][0], ahi[mt][1], ahi[mt][2], ahi[mt][3], ad);
                LDSM_X4(alo[mt][0], alo[mt][1], alo[mt][2], alo[mt][3], ad + OFF_ALO);
            }
#pragma unroll
            for (int p = 0; p < 2; p++) {
                unsigned bd = stg + OFF_BHI + b_row_byte + (unsigned)(p * 1024) + bch;
                LDSM_X4(bh[p][0], bh[p][1], bh[p][2], bh[p][3], bd);
                LDSM_X4(bl[p][0], bl[p][1], bl[p][2], bl[p][3], bd + (OFF_BLO - OFF_BHI));
            }
            // hi * hi
#pragma unroll
            for (int mt = 0; mt < 4; mt++)
#pragma unroll
                for (int p = 0; p < 2; p++) {
                    mma_bf16(acc[mt][2 * p + 0], ahi[mt], &bh[p][0]);
                    mma_bf16(acc[mt][2 * p + 1], ahi[mt], &bh[p][2]);
                }
            // hi * lo
#pragma unroll
            for (int mt = 0; mt < 4; mt++)
#pragma unroll
                for (int p = 0; p < 2; p++) {
                    mma_bf16(acc[mt][2 * p + 0], ahi[mt], &bl[p][0]);
                    mma_bf16(acc[mt][2 * p + 1], ahi[mt], &bl[p][2]);
                }
            // lo * hi
#pragma unroll
            for (int mt = 0; mt < 4; mt++)
#pragma unroll
                for (int p = 0; p < 2; p++) {
                    mma_bf16(acc[mt][2 * p + 0], alo[mt], &bh[p][0]);
                    mma_bf16(acc[mt][2 * p + 1], alo[mt], &bh[p][2]);
                }
        }
        if (++st == NSTAGE) st = 0;
    }

#pragma unroll
    for (int mt = 0; mt < 4; mt++) {
        const int mrow = m0 + warp_m * 64 + mt * 16 + grp;
#pragma unroll
        for (int nt = 0; nt < 4; nt++) {
            const int col = n0 + warp_n * 32 + nt * 8 + 2 * qid;
            float b0 = bias ? bias[col] : 0.f;
            float b1 = bias ? bias[col + 1] : 0.f;
            float2 v0 = make_float2(acc[mt][nt][0] + b0, acc[mt][nt][1] + b1);
            float2 v1 = make_float2(acc[mt][nt][2] + b0, acc[mt][nt][3] + b1);
            *(float2*)(C + (size_t)mrow * N + col) = v0;
            *(float2*)(C + (size_t)(mrow + 8) * N + col) = v1;
        }
    }
}

// ---------------- fused RoPE + split + relayout ----------------
__global__ void rope_split_kernel(const float* __restrict__ qkv,
                                  const int* __restrict__ positions)
{
    int idx = blockIdx.x * blockDim.x + threadIdx.x;
    if (idx >= MROWS * NHEAD * 64) return;
    const int i = idx & 63;
    const int h = (idx >> 6) & 31;
    const int m = idx >> 11;
    const int b = m >> 11;
    const int s = m & 2047;

    const float pos = (float)positions[m];
    const float inv_freq = powf(10000.0f, -(float)i / 64.0f);
    const float ang = pos * inv_freq;
    const float c = cosf(ang);
    const float sn = sinf(ang);

    const float* row = qkv + (size_t)m * QKV_N + h * HDIM;
    const size_t hb = ((size_t)((b * NHEAD + h) * SLEN) + s) * HDIM;

    {
        float x1 = row[i], x2 = row[i + 64];
        float y1 = x1 * c - x2 * sn;
        float y2 = x2 * c + x1 * sn;
        __nv_bfloat16 h1, l1, h2, l2;
        split_bf16(y1, h1, l1); split_bf16(y2, h2, l2);
        g_q_hi[hb + i] = h1; g_q_hi[hb + i + 64] = h2;
        g_q_lo[hb + i] = l1; g_q_lo[hb + i + 64] = l2;
    }
    {
        float x1 = row[HID + i], x2 = row[HID + i + 64];
        float y1 = x1 * c - x2 * sn;
        float y2 = x2 * c + x1 * sn;
        __nv_bfloat16 h1, l1, h2, l2;
        split_bf16(y1, h1, l1); split_bf16(y2, h2, l2);
        g_k_hi[hb + i] = h1; g_k_hi[hb + i + 64] = h2;
        g_k_lo[hb + i] = l1; g_k_lo[hb + i + 64] = l2;
    }
    {
        float x1 = row[2 * HID + i], x2 = row[2 * HID + i + 64];
        __nv_bfloat16 h1, l1, h2, l2;
        split_bf16(x1, h1, l1); split_bf16(x2, h2, l2);
        g_v_hi[hb + i] = h1; g_v_hi[hb + i + 64] = h2;
        g_v_lo[hb + i] = l1; g_v_lo[hb + i + 64] = l2;
    }
}

// ---------------- tensor-core flash attention (bf16-split, causal) ----------------
#define AQT 128
#define AKT 64
#define QST 136
#define KST 136
#define VST 72
#define SM_QHI 0
#define SM_QLO (SM_QHI + AQT * QST)
#define SM_KHI (SM_QLO + AQT * QST)
#define SM_KLO (SM_KHI + AKT * KST)
#define SM_VHI (SM_KLO + AKT * KST)
#define SM_VLO (SM_VHI + AQT * VST)
#define ATT_SMEM_ELEMS (SM_VLO + AQT * VST)
#define ATT_SMEM_BYTES (ATT_SMEM_ELEMS * 2)   // 141312

__global__ __launch_bounds__(256)
void flash_mma_kernel(const __nv_bfloat16* __restrict__ qh, const __nv_bfloat16* __restrict__ ql,
                      const __nv_bfloat16* __restrict__ kh, const __nv_bfloat16* __restrict__ kl,
                      const __nv_bfloat16* __restrict__ vh, const __nv_bfloat16* __restrict__ vl,
                      __nv_bfloat16* __restrict__ ctx_hi, __nv_bfloat16* __restrict__ ctx_lo)
{
    extern __shared__ __nv_bfloat16 sma[];
    const int qt = blockIdx.x;
    const int h  = blockIdx.y;
    const int b  = blockIdx.z;
    const int tid = threadIdx.x;
    const int wid = tid >> 5;
    const int lane = tid & 31;
    const int grp = lane >> 2;
    const int qid = lane & 3;
    const size_t hb = ((size_t)(b * NHEAD + h)) * SLEN * HDIM;
    unsigned sbase = (unsigned)__cvta_generic_to_shared(sma);
    const float scale = 0.08838834764831845f;

    {
        const __nv_bfloat16* g = qh + hb + (size_t)qt * AQT * HDIM;
#pragma unroll
        for (int p = 0; p < 8; p++) {
            int i = p * 256 + tid;
            int row = i >> 4, c = i & 15;
            CP_ASYNC16(sbase + (unsigned)(SM_QHI + row * QST + c * 8) * 2u, g + row * HDIM + c * 8);
        }
        g = ql + hb + (size_t)qt * AQT * HDIM;
#pragma unroll
        for (int p = 0; p < 8; p++) {
            int i = p * 256 + tid;
            int row = i >> 4, c = i & 15;
            CP_ASYNC16(sbase + (unsigned)(SM_QLO + row * QST + c * 8) * 2u, g + row * HDIM + c * 8);
        }
        CP_COMMIT();
    }

    float m0 = -1e30f, m1 = -1e30f, l0 = 0.f, l1 = 0.f;
    float o[16][4];
#pragma unroll
    for (int nt = 0; nt < 16; nt++)
#pragma unroll
        for (int r = 0; r < 4; r++) o[nt][r] = 0.f;

    const int qrow_warp = qt * AQT + wid * 16;
    const int nkt = 2 * qt + 2;

    for (int kt = 0; kt < nkt; kt++) {
        __syncthreads();
        {
            const __nv_bfloat16* g = kh + hb + (size_t)kt * AKT * HDIM;
#pragma unroll
            for (int p = 0; p < 4; p++) {
                int i = p * 256 + tid;
                int row = i >> 4, c = i & 15;
                CP_ASYNC16(sbase + (unsigned)(SM_KHI + row * KST + c * 8) * 2u, g + row * HDIM + c * 8);
            }
            g = kl + hb + (size_t)kt * AKT * HDIM;
#pragma unroll
            for (int p = 0; p < 4; p++) {
                int i = p * 256 + tid;
                int row = i >> 4, c = i & 15;
                CP_ASYNC16(sbase + (unsigned)(SM_KLO + row * KST + c * 8) * 2u, g + row * HDIM + c * 8);
            }
            CP_COMMIT();
        }
        {
            const int kv = tid & 63;
            const int dg = tid >> 6;
            uint4 tv[4];
            const __nv_bfloat16* g = vh + hb + (size_t)(kt * AKT + kv) * HDIM + dg * 32;
#pragma unroll
            for (int c = 0; c < 4; c++) tv[c] = *(const uint4*)(g + c * 8);
            const __nv_bfloat16* tb = (const __nv_bfloat16*)tv;
#pragma unroll
            for (int j = 0; j < 32; j++)
                sma[SM_VHI + (dg * 32 + j) * VST + kv] = tb[j];
            g = vl + hb + (size_t)(kt * AKT + kv) * HDIM + dg * 32;
#pragma unroll
            for (int c = 0; c < 4; c++) tv[c] = *(const uint4*)(g + c * 8);
#pragma unroll
            for (int j = 0; j < 32; j++)
                sma[SM_VLO + (dg * 32 + j) * VST + kv] = tb[j];
        }
        CP_WAIT(0);
        __syncthreads();

        const bool active = (kt * AKT <= qrow_warp + 15);
        if (active) {
            float sreg[8][4];
#pragma unroll
            for (int nt = 0; nt < 8; nt++)
#pragma unroll
                for (int r = 0; r < 4; r++) sreg[nt][r] = 0.f;

#pragma unroll
            for (int d8 = 0; d8 < 8; d8++) {
                const int kof = d8 * 16 + 2 * qid;
                unsigned ahi[4], alo[4];
                {
                    const __nv_bfloat16* p = sma + SM_QHI + (wid * 16 + grp) * QST + kof;
                    ahi[0] = *(const unsigned*)(p);
                    ahi[1] = *(const unsigned*)(p + 8 * QST);
                    ahi[2] = *(const unsigned*)(p + 8);
                    ahi[3] = *(const unsigned*)(p + 8 * QST + 8);
                    const __nv_bfloat16* pl = sma + SM_QLO + (wid * 16 + grp) * QST + kof;
                    alo[0] = *(const unsigned*)(pl);
                    alo[1] = *(const unsigned*)(pl + 8 * QST);
                    alo[2] = *(const unsigned*)(pl + 8);
                    alo[3] = *(const unsigned*)(pl + 8 * QST + 8);
                }
#pragma unroll
                for (int nt = 0; nt < 8; nt++) {
                    unsigned bhi[2], blo[2];
                    const __nv_bfloat16* p = sma + SM_KHI + (nt * 8 + grp) * KST + kof;
                    bhi[0] = *(const unsigned*)(p);
                    bhi[1] = *(const unsigned*)(p + 8);
                    const __nv_bfloat16* pl = sma + SM_KLO + (nt * 8 + grp) * KST + kof;
                    blo[0] = *(const unsigned*)(pl);
                    blo[1] = *(const unsigned*)(pl + 8);
                    mma_bf16(sreg[nt], ahi, bhi);
                    mma_bf16(sreg[nt], ahi, blo);
                    mma_bf16(sreg[nt], alo, bhi);
                }
            }

            const int row0 = qrow_warp + grp;
            const int row1 = row0 + 8;
#pragma unroll
            for (int nt = 0; nt < 8; nt++) {
                const int c0 = kt * AKT + nt * 8 + 2 * qid;
                const int c1 = c0 + 1;
                sreg[nt][0] = (c0 <= row0) ? sreg[nt][0] * scale : -1e30f;
                sreg[nt][1] = (c1 <= row0) ? sreg[nt][1] * scale : -1e30f;
                sreg[nt][2] = (c0 <= row1) ? sreg[nt][2] * scale : -1e30f;
                sreg[nt][3] = (c1 <= row1) ? sreg[nt][3] * scale : -1e30f;
            }

            float tm0 = -1e30f, tm1 = -1e30f;
#pragma unroll
            for (int nt = 0; nt < 8; nt++) {
                tm0 = fmaxf(tm0, fmaxf(sreg[nt][0], sreg[nt][1]));
                tm1 = fmaxf(tm1, fmaxf(sreg[nt][2], sreg[nt][3]));
            }
            tm0 = fmaxf(tm0, __shfl_xor_sync(0xffffffffu, tm0, 1));
            tm0 = fmaxf(tm0, __shfl_xor_sync(0xffffffffu, tm0, 2));
            tm1 = fmaxf(tm1, __shfl_xor_sync(0xffffffffu, tm1, 1));
            tm1 = fmaxf(tm1, __shfl_xor_sync(0xffffffffu, tm1, 2));
            const float mn0 = fmaxf(m0, tm0);
            const float mn1 = fmaxf(m1, tm1);
            const float al0 = __expf(m0 - mn0);
            const float al1 = __expf(m1 - mn1);
            m0 = mn0; m1 = mn1;
            float ps0 = 0.f, ps1 = 0.f;
#pragma unroll
            for (int nt = 0; nt < 8; nt++) {
                sreg[nt][0] = __expf(sreg[nt][0] - m0);
                sreg[nt][1] = __expf(sreg[nt][1] - m0);
                sreg[nt][2] = __expf(sreg[nt][2] - m1);
                sreg[nt][3] = __expf(sreg[nt][3] - m1);
                ps0 += sreg[nt][0] + sreg[nt][1];
                ps1 += sreg[nt][2] + sreg[nt][3];
            }
            l0 = l0 * al0 + ps0;
            l1 = l1 * al1 + ps1;
#pragma unroll
            for (int nt = 0; nt < 16; nt++) {
                o[nt][0] *= al0; o[nt][1] *= al0;
                o[nt][2] *= al1; o[nt][3] *= al1;
            }

#pragma unroll
            for (int c = 0; c < 4; c++) {
                unsigned phi[4], plo[4];
#pragma unroll
                for (int half = 0; half < 2; half++) {
                    const float x0 = sreg[2 * c + half][0];
                    const float x1 = sreg[2 * c + half][1];
                    const float x2 = sreg[2 * c + half][2];
                    const float x3 = sreg[2 * c + half][3];
                    __nv_bfloat16 h0 = __float2bfloat16(x0);
                    __nv_bfloat16 h1 = __float2bfloat16(x1);
                    __nv_bfloat16 h2 = __float2bfloat16(x2);
                    __nv_bfloat16 h3 = __float2bfloat16(x3);
                    phi[0 + 2 * half] = pack_bf16x2(__bfloat162float(h0), __bfloat162float(h1));
                    phi[1 + 2 * half] = pack_bf16x2(__bfloat162float(h2), __bfloat162float(h3));
                    plo[0 + 2 * half] = pack_bf16x2(x0 - __bfloat162float(h0), x1 - __bfloat162float(h1));
                    plo[1 + 2 * half] = pack_bf16x2(x2 - __bfloat162float(h2), x3 - __bfloat162float(h3));
                }
                const int kof = 2 * qid + 16 * c;
#pragma unroll
                for (int nt = 0; nt < 16; nt++) {
                    unsigned bhi[2], blo[2];
                    const __nv_bfloat16* p = sma + SM_VHI + (nt * 8 + grp) * VST + kof;
                    bhi[0] = *(const unsigned*)(p);
                    bhi[1] = *(const unsigned*)(p + 8);
                    const __nv_bfloat16* pl = sma + SM_VLO + (nt * 8 + grp) * VST + kof;
                    blo[0] = *(const unsigned*)(pl);
                    blo[1] = *(const unsigned*)(pl + 8);
                    mma_bf16(o[nt], phi, bhi);
                    mma_bf16(o[nt], plo, bhi);
                    mma_bf16(o[nt], phi, blo);
                }
            }
        }
    }

    l0 += __shfl_xor_sync(0xffffffffu, l0, 1);
    l0 += __shfl_xor_sync(0xffffffffu, l0, 2);
    l1 += __shfl_xor_sync(0xffffffffu, l1, 1);
    l1 += __shfl_xor_sync(0xffffffffu, l1, 2);
    const float inv0 = 1.0f / l0;
    const float inv1 = 1.0f / l1;

    const int row0 = b * SLEN + qt * AQT + wid * 16 + grp;
#pragma unroll
    for (int nt = 0; nt < 16; nt++) {
        const int col = h * HDIM + nt * 8 + 2 * qid;
        float v0 = o[nt][0] * inv0, v1 = o[nt][1] * inv0;
        float v2 = o[nt][2] * inv1, v3 = o[nt][3] * inv1;
        __nv_bfloat16 h0, l0b, h1, l1b, h2, l2b, h3, l3b;
        split_bf16(v0, h0, l0b); split_bf16(v1, h1, l1b);
        split_bf16(v2, h2, l2b); split_bf16(v3, h3, l3b);
        *(__nv_bfloat162*)(ctx_hi + (size_t)row0 * HID + col) = __nv_bfloat162(h0, h1);
        *(__nv_bfloat162*)(ctx_lo + (size_t)row0 * HID + col) = __nv_bfloat162(l0b, l1b);
        *(__nv_bfloat162*)(ctx_hi + (size_t)(row0 + 8) * HID + col) = __nv_bfloat162(h2, h3);
        *(__nv_bfloat162*)(ctx_lo + (size_t)(row0 + 8) * HID + col) = __nv_bfloat162(l2b, l3b);
    }
}

// ---------------- launch ----------------
extern "C" void kernel_launch(void* const* d_in, const int* in_sizes, int n_in,
                              void* d_out, int out_size)
{
    const float* hs    = (const float*)d_in[0];
    const int*   pos   = (const int*)d_in[1];
    const float* Wqkv  = (const float*)d_in[2];
    const float* bqkv  = (const float*)d_in[3];
    const float* Wo    = (const float*)d_in[4];
    float* out = (float*)d_out;

    float *qkv;
    __nv_bfloat16 *hs_hi, *hs_lo, *ctx_hi, *ctx_lo, *wqkv_hi, *wqkv_lo, *wo_hi, *wo_lo;
    __nv_bfloat16 *q_hi, *q_lo, *k_hi, *k_lo, *v_hi, *v_lo;
    cudaGetSymbolAddress((void**)&qkv, g_qkv);
    cudaGetSymbolAddress((void**)&hs_hi, g_hs_hi);
    cudaGetSymbolAddress((void**)&hs_lo, g_hs_lo);
    cudaGetSymbolAddress((void**)&ctx_hi, g_ctx_hi);
    cudaGetSymbolAddress((void**)&ctx_lo, g_ctx_lo);
    cudaGetSymbolAddress((void**)&wqkv_hi, g_wqkv_hi);
    cudaGetSymbolAddress((void**)&wqkv_lo, g_wqkv_lo);
    cudaGetSymbolAddress((void**)&wo_hi, g_wo_hi);
    cudaGetSymbolAddress((void**)&wo_lo, g_wo_lo);
    cudaGetSymbolAddress((void**)&q_hi, g_q_hi);
    cudaGetSymbolAddress((void**)&q_lo, g_q_lo);
    cudaGetSymbolAddress((void**)&k_hi, g_k_hi);
    cudaGetSymbolAddress((void**)&k_lo, g_k_lo);
    cudaGetSymbolAddress((void**)&v_hi, g_v_hi);
    cudaGetSymbolAddress((void**)&v_lo, g_v_lo);

    static int configured = 0;
    if (!configured) {
        cudaFuncSetAttribute(gemm_bf16split_kernel,
                             cudaFuncAttributeMaxDynamicSharedMemorySize, GEMM_SMEM_BYTES);
        cudaFuncSetAttribute(flash_mma_kernel,
                             cudaFuncAttributeMaxDynamicSharedMemorySize, ATT_SMEM_BYTES);
        configured = 1;
    }

    // 0) splits + weight transposes
    {
        int n4 = MROWS * HID / 4;
        split_kernel<<<(n4 + 255) / 256, 256>>>(hs, hs_hi, hs_lo, n4);
        dim3 g1(QKV_N / 32, HID / 32);
        transpose_split_kernel<<<g1, dim3(32, 8)>>>(Wqkv, wqkv_hi, wqkv_lo, HID, QKV_N);
        dim3 g2(HID / 32, HID / 32);
        transpose_split_kernel<<<g2, dim3(32, 8)>>>(Wo, wo_hi, wo_lo, HID, HID);
    }
    // 1) qkv = hs @ W_qkv + b
    {
        dim3 grid(QKV_N / BN, MROWS / BM);   // (96, 32)
        gemm_bf16split_kernel<<<grid, 256, GEMM_SMEM_BYTES>>>(
            hs_hi, hs_lo, wqkv_hi, wqkv_lo, bqkv, qkv, MROWS, QKV_N, HID);
    }
    // 2) RoPE + split + relayout
    {
        int total = MROWS * NHEAD * 64;
        rope_split_kernel<<<(total + 255) / 256, 256>>>(qkv, pos);
    }
    // 3) flash attention -> ctx hi/lo bf16
    {
        dim3 grid(SLEN / AQT, NHEAD, BATCH);   // (16, 32, 2)
        flash_mma_kernel<<<grid, 256, ATT_SMEM_BYTES>>>(q_hi, q_lo, k_hi, k_lo,
                                                        v_hi, v_lo, ctx_hi, ctx_lo);
    }
    // 4) out = ctx @ W_o
    {
        dim3 grid(HID / BN, MROWS / BM);     // (32, 32)
        gemm_bf16split_kernel<<<grid, 256, GEMM_SMEM_BYTES>>>(
            ctx_hi, ctx_lo, wo_hi, wo_lo, nullptr, out, MROWS, HID, HID);
    }
}

// round 14
// speedup vs baseline: 1.3191x; 1.0575x over previous
#include <cuda_runtime.h>
#include <cuda_bf16.h>
#include <math.h>

// Problem constants
#define BATCH 2
#define SLEN 2048
#define HID 4096
#define NHEAD 32
#define HDIM 128
#define MROWS (BATCH * SLEN)       // 4096
#define QKV_N (3 * HID)            // 12288

// ---------------- scratch (no allocations allowed) ----------------
__device__ float g_qkv[(size_t)MROWS * QKV_N];   // 201 MB
__device__ __nv_bfloat16 g_hs_hi[(size_t)MROWS * HID];
__device__ __nv_bfloat16 g_hs_lo[(size_t)MROWS * HID];
__device__ __nv_bfloat16 g_ctx_hi[(size_t)MROWS * HID];
__device__ __nv_bfloat16 g_ctx_lo[(size_t)MROWS * HID];
__device__ __nv_bfloat16 g_wqkv_hi[(size_t)QKV_N * HID];   // transposed [N][K]
__device__ __nv_bfloat16 g_wqkv_lo[(size_t)QKV_N * HID];
__device__ __nv_bfloat16 g_wo_hi[(size_t)HID * HID];       // transposed [N][K]
__device__ __nv_bfloat16 g_wo_lo[(size_t)HID * HID];
__device__ __nv_bfloat16 g_q_hi[(size_t)MROWS * HID];
__device__ __nv_bfloat16 g_q_lo[(size_t)MROWS * HID];
__device__ __nv_bfloat16 g_k_hi[(size_t)MROWS * HID];
__device__ __nv_bfloat16 g_k_lo[(size_t)MROWS * HID];
__device__ __nv_bfloat16 g_v_hi[(size_t)MROWS * HID];
__device__ __nv_bfloat16 g_v_lo[(size_t)MROWS * HID];

// ---------------- helpers ----------------
__device__ __forceinline__ void split_bf16(float x, __nv_bfloat16& h, __nv_bfloat16& l)
{
    h = __float2bfloat16(x);
    l = __float2bfloat16(x - __bfloat162float(h));
}

__device__ __forceinline__ unsigned pack_bf16x2(float x, float y)
{
    unsigned r;
    asm("cvt.rn.bf16x2.f32 %0, %1, %2;" : "=r"(r) : "f"(y), "f"(x));
    return r;
}

#define CP_ASYNC16(dst, src) \
    asm volatile("cp.async.cg.shared.global [%0], [%1], 16;\n" :: "r"(dst), "l"(src))
#define CP_COMMIT() asm volatile("cp.async.commit_group;\n" ::: "memory")
#define CP_WAIT(n)  asm volatile("cp.async.wait_group %0;\n" :: "n"(n) : "memory")

#define LDSM_X4(r0, r1, r2, r3, addr) \
    asm volatile("ldmatrix.sync.aligned.m8n8.x4.shared.b16 {%0,%1,%2,%3}, [%4];" \
        : "=r"(r0), "=r"(r1), "=r"(r2), "=r"(r3) : "r"(addr))

#define LDSM_X4_T(r0, r1, r2, r3, addr) \
    asm volatile("ldmatrix.sync.aligned.m8n8.x4.trans.shared.b16 {%0,%1,%2,%3}, [%4];" \
        : "=r"(r0), "=r"(r1), "=r"(r2), "=r"(r3) : "r"(addr))

__device__ __forceinline__ void mma_bf16(float* c, const unsigned* a, const unsigned* b)
{
    asm volatile(
        "mma.sync.aligned.m16n8k16.row.col.f32.bf16.bf16.f32 "
        "{%0,%1,%2,%3},{%4,%5,%6,%7},{%8,%9},{%0,%1,%2,%3};"
        : "+f"(c[0]), "+f"(c[1]), "+f"(c[2]), "+f"(c[3])
        : "r"(a[0]), "r"(a[1]), "r"(a[2]), "r"(a[3]), "r"(b[0]), "r"(b[1]));
}

// ---------------- split / transpose kernels ----------------
__global__ void split_kernel(const float* __restrict__ src,
                             __nv_bfloat16* __restrict__ hi,
                             __nv_bfloat16* __restrict__ lo, int n4)
{
    int i = blockIdx.x * blockDim.x + threadIdx.x;
    if (i >= n4) return;
    float4 v = ((const float4*)src)[i];
    __nv_bfloat16 h0, h1, h2, h3, l0, l1, l2, l3;
    split_bf16(v.x, h0, l0); split_bf16(v.y, h1, l1);
    split_bf16(v.z, h2, l2); split_bf16(v.w, h3, l3);
    __nv_bfloat162* hp = (__nv_bfloat162*)(hi + (size_t)i * 4);
    __nv_bfloat162* lp = (__nv_bfloat162*)(lo + (size_t)i * 4);
    hp[0] = __nv_bfloat162(h0, h1); hp[1] = __nv_bfloat162(h2, h3);
    lp[0] = __nv_bfloat162(l0, l1); lp[1] = __nv_bfloat162(l2, l3);
}

__global__ void transpose_split_kernel(const float* __restrict__ W,
                                       __nv_bfloat16* __restrict__ hi,
                                       __nv_bfloat16* __restrict__ lo,
                                       int K, int N)
{
    __shared__ float t[32][33];
    const int n0 = blockIdx.x * 32;
    const int k0 = blockIdx.y * 32;
    const int tx = threadIdx.x;
    const int ty = threadIdx.y;
#pragma unroll
    for (int j = 0; j < 32; j += 8)
        t[ty + j][tx] = W[(size_t)(k0 + ty + j) * N + n0 + tx];
    __syncthreads();
#pragma unroll
    for (int j = 0; j < 32; j += 8) {
        float x = t[tx][ty + j];
        __nv_bfloat16 h, l;
        split_bf16(x, h, l);
        size_t o = (size_t)(n0 + ty + j) * K + k0 + tx;
        hi[o] = h;
        lo[o] = l;
    }
}

// ===== bf16-split GEMM: 128x128, XOR-swizzled smem, 3-stage, 1 barrier/iter =====
#define BM 128
#define BN 128
#define BK 32
#define A_TILE_BYTES 8192
#define OFF_ALO 8192
#define OFF_BHI 16384
#define OFF_BLO 24576
#define STAGE_BYTES 32768
#define NSTAGE 3
#define GEMM_SMEM_BYTES (NSTAGE * STAGE_BYTES)   // 98304 per CTA (2 CTA/SM)

__global__ __launch_bounds__(256)
void gemm_bf16split_kernel(const __nv_bfloat16* __restrict__ Ahi,
                           const __nv_bfloat16* __restrict__ Alo,
                           const __nv_bfloat16* __restrict__ Bhi,
                           const __nv_bfloat16* __restrict__ Blo,
                           const float* __restrict__ bias, float* __restrict__ C,
                           int M, int N, int K)
{
    extern __shared__ __nv_bfloat16 sm[];
    const int tid = threadIdx.x;
    const int wid = tid >> 5;
    const int lane = tid & 31;
    const int grp = lane >> 2;
    const int qid = lane & 3;
    const int warp_m = wid >> 2;
    const int warp_n = wid & 3;

    const int m0 = blockIdx.y * BM;
    const int n0 = blockIdx.x * BN;

    float acc[4][4][4];
#pragma unroll
    for (int i = 0; i < 4; i++)
#pragma unroll
        for (int j = 0; j < 4; j++)
#pragma unroll
            for (int r = 0; r < 4; r++) acc[i][j][r] = 0.f;

    unsigned smem_base = (unsigned)__cvta_generic_to_shared(sm);
    const int NIT = K / BK;

    const unsigned asw = ((unsigned)(lane & 15) >> 1) & 3;
    const unsigned bsw = ((unsigned)(lane & 7) >> 1) & 3;
    const unsigned a_row_byte = (unsigned)(warp_m * 64 + (lane & 15)) * 64u;
    const unsigned a_c0 = ((unsigned)lane >> 4) & 1;
    const unsigned b_row_byte = (unsigned)(warp_n * 32 + ((lane >> 4) & 1) * 8 + (lane & 7)) * 64u;
    const unsigned b_c0 = ((unsigned)lane >> 3) & 1;

    auto load_stage = [&](int st, int k0) {
        unsigned sb = smem_base + (unsigned)(st * STAGE_BYTES);
        const __nv_bfloat16* gsrc[4] = {Ahi, Alo, Bhi, Blo};
        const int gm0[4] = {m0, m0, n0, n0};
#pragma unroll
        for (int arr = 0; arr < 4; arr++) {
            unsigned sa = sb + (unsigned)(arr * A_TILE_BYTES);
            const __nv_bfloat16* g = gsrc[arr];
#pragma unroll
            for (int p = 0; p < 2; p++) {
                int i = p * 256 + tid;
                unsigned row = (unsigned)(i >> 2);
                unsigned c = (unsigned)(i & 3);
                unsigned dst = sa + row * 64u + ((c ^ ((row >> 1) & 3)) << 4);
                CP_ASYNC16(dst, g + (size_t)(gm0[arr] + (int)row) * K + k0 + (int)c * 8);
            }
        }
    };

    load_stage(0, 0);
    CP_COMMIT();
    load_stage(1, BK);
    CP_COMMIT();

    int st = 0;
    for (int it = 0; it < NIT; it++) {
        if (it + 1 < NIT) { CP_WAIT(1); } else { CP_WAIT(0); }
        __syncthreads();
        if (it + 2 < NIT) {
            int s2 = st + 2; if (s2 >= NSTAGE) s2 -= NSTAGE;
            load_stage(s2, (it + 2) * BK);
            CP_COMMIT();
        }

        const unsigned stg = smem_base + (unsigned)(st * STAGE_BYTES);

#pragma unroll
        for (int kk = 0; kk < 2; kk++) {
            unsigned ahi[4][4], alo[4][4], bh[2][4], bl[2][4];
            const unsigned ach = (((unsigned)(kk * 2) + a_c0) ^ asw) << 4;
            const unsigned bch = (((unsigned)(kk * 2) + b_c0) ^ bsw) << 4;
#pragma unroll
            for (int mt = 0; mt < 4; mt++) {
                unsigned ad = stg + a_row_byte + (unsigned)(mt * 1024) + ach;
                LDSM_X4(ahi[mt][0], ahi[mt][1], ahi[mt][2], ahi[mt][3], ad);
                LDSM_X4(alo[mt][0], alo[mt][1], alo[mt][2], alo[mt][3], ad + OFF_ALO);
            }
#pragma unroll
            for (int p = 0; p < 2; p++) {
                unsigned bd = stg + OFF_BHI + b_row_byte + (unsigned)(p * 1024) + bch;
                LDSM_X4(bh[p][0], bh[p][1], bh[p][2], bh[p][3], bd);
                LDSM_X4(bl[p][0], bl[p][1], bl[p][2], bl[p][3], bd + (OFF_BLO - OFF_BHI));
            }
#pragma unroll
            for (int mt = 0; mt < 4; mt++)
#pragma unroll
                for (int p = 0; p < 2; p++) {
                    mma_bf16(acc[mt][2 * p + 0], ahi[mt], &bh[p][0]);
                    mma_bf16(acc[mt][2 * p + 1], ahi[mt], &bh[p][2]);
                }
#pragma unroll
            for (int mt = 0; mt < 4; mt++)
#pragma unroll
                for (int p = 0; p < 2; p++) {
                    mma_bf16(acc[mt][2 * p + 0], ahi[mt], &bl[p][0]);
                    mma_bf16(acc[mt][2 * p + 1], ahi[mt], &bl[p][2]);
                }
#pragma unroll
            for (int mt = 0; mt < 4; mt++)
#pragma unroll
                for (int p = 0; p < 2; p++) {
                    mma_bf16(acc[mt][2 * p + 0], alo[mt], &bh[p][0]);
                    mma_bf16(acc[mt][2 * p + 1], alo[mt], &bh[p][2]);
                }
        }
        if (++st == NSTAGE) st = 0;
    }

#pragma unroll
    for (int mt = 0; mt < 4; mt++) {
        const int mrow = m0 + warp_m * 64 + mt * 16 + grp;
#pragma unroll
        for (int nt = 0; nt < 4; nt++) {
            const int col = n0 + warp_n * 32 + nt * 8 + 2 * qid;
            float b0 = bias ? bias[col] : 0.f;
            float b1 = bias ? bias[col + 1] : 0.f;
            float2 v0 = make_float2(acc[mt][nt][0] + b0, acc[mt][nt][1] + b1);
            float2 v1 = make_float2(acc[mt][nt][2] + b0, acc[mt][nt][3] + b1);
            *(float2*)(C + (size_t)mrow * N + col) = v0;
            *(float2*)(C + (size_t)(mrow + 8) * N + col) = v1;
        }
    }
}

// ---------------- fused RoPE + split + relayout ----------------
__global__ void rope_split_kernel(const float* __restrict__ qkv,
                                  const int* __restrict__ positions)
{
    int idx = blockIdx.x * blockDim.x + threadIdx.x;
    if (idx >= MROWS * NHEAD * 64) return;
    const int i = idx & 63;
    const int h = (idx >> 6) & 31;
    const int m = idx >> 11;
    const int b = m >> 11;
    const int s = m & 2047;

    const float pos = (float)positions[m];
    const float inv_freq = powf(10000.0f, -(float)i / 64.0f);
    const float ang = pos * inv_freq;
    const float c = cosf(ang);
    const float sn = sinf(ang);

    const float* row = qkv + (size_t)m * QKV_N + h * HDIM;
    const size_t hb = ((size_t)((b * NHEAD + h) * SLEN) + s) * HDIM;

    {
        float x1 = row[i], x2 = row[i + 64];
        float y1 = x1 * c - x2 * sn;
        float y2 = x2 * c + x1 * sn;
        __nv_bfloat16 h1, l1, h2, l2;
        split_bf16(y1, h1, l1); split_bf16(y2, h2, l2);
        g_q_hi[hb + i] = h1; g_q_hi[hb + i + 64] = h2;
        g_q_lo[hb + i] = l1; g_q_lo[hb + i + 64] = l2;
    }
    {
        float x1 = row[HID + i], x2 = row[HID + i + 64];
        float y1 = x1 * c - x2 * sn;
        float y2 = x2 * c + x1 * sn;
        __nv_bfloat16 h1, l1, h2, l2;
        split_bf16(y1, h1, l1); split_bf16(y2, h2, l2);
        g_k_hi[hb + i] = h1; g_k_hi[hb + i + 64] = h2;
        g_k_lo[hb + i] = l1; g_k_lo[hb + i + 64] = l2;
    }
    {
        float x1 = row[2 * HID + i], x2 = row[2 * HID + i + 64];
        __nv_bfloat16 h1, l1, h2, l2;
        split_bf16(x1, h1, l1); split_bf16(x2, h2, l2);
        g_v_hi[hb + i] = h1; g_v_hi[hb + i + 64] = h2;
        g_v_lo[hb + i] = l1; g_v_lo[hb + i + 64] = l2;
    }
}

// ====== tensor-core flash attention: LDSM fragments, double-buffered K/V ======
#define AQT 128
#define AKT 64
#define APITCH 136                       // elems; 272B rows -> conflict-free LDSM
#define SM_QHI 0
#define SM_QLO (AQT * APITCH)            // 17408
#define SM_ST0 (2 * AQT * APITCH)        // 34816
#define STG_TILE (AKT * APITCH)          // 8704
#define STG_K_LO STG_TILE
#define STG_V_HI (2 * STG_TILE)
#define STG_V_LO (3 * STG_TILE)
#define STG_ELEMS (4 * STG_TILE)         // 34816
#define ATT_SMEM_ELEMS (SM_ST0 + 2 * STG_ELEMS)  // 104448
#define ATT_SMEM_BYTES (ATT_SMEM_ELEMS * 2)      // 208896

__global__ __launch_bounds__(256)
void flash_mma_kernel(const __nv_bfloat16* __restrict__ qh, const __nv_bfloat16* __restrict__ ql,
                      const __nv_bfloat16* __restrict__ kh, const __nv_bfloat16* __restrict__ kl,
                      const __nv_bfloat16* __restrict__ vh, const __nv_bfloat16* __restrict__ vl,
                      __nv_bfloat16* __restrict__ ctx_hi, __nv_bfloat16* __restrict__ ctx_lo)
{
    extern __shared__ __nv_bfloat16 sma[];
    const int qt = blockIdx.x;
    const int h  = blockIdx.y;
    const int b  = blockIdx.z;
    const int tid = threadIdx.x;
    const int wid = tid >> 5;
    const int lane = tid & 31;
    const int grp = lane >> 2;
    const int qid = lane & 3;
    const size_t hb = ((size_t)(b * NHEAD + h)) * SLEN * HDIM;
    unsigned sbase = (unsigned)__cvta_generic_to_shared(sma);
    const float scale = 0.08838834764831845f;

    // Q tile loads: 128 rows x 16 chunks x 2 arrays
    {
        const __nv_bfloat16* gq[2] = {qh + hb + (size_t)qt * AQT * HDIM,
                                      ql + hb + (size_t)qt * AQT * HDIM};
        const unsigned qoff[2] = {SM_QHI, SM_QLO};
#pragma unroll
        for (int arr = 0; arr < 2; arr++)
#pragma unroll
            for (int p = 0; p < 8; p++) {
                int i = p * 256 + tid;
                int row = i >> 4, c = i & 15;
                CP_ASYNC16(sbase + (unsigned)(qoff[arr] + row * APITCH + c * 8) * 2u,
                           gq[arr] + row * HDIM + c * 8);
            }
        CP_COMMIT();
    }

    // K/V stage loader: 4 arrays x 64 rows x 16 chunks = 4096 chunks / 256 = 16/thread
    auto load_kv = [&](int st, int kt) {
        const unsigned sb = (unsigned)(SM_ST0 + st * STG_ELEMS);
        const __nv_bfloat16* gs[4] = {kh + hb + (size_t)kt * AKT * HDIM,
                                      kl + hb + (size_t)kt * AKT * HDIM,
                                      vh + hb + (size_t)kt * AKT * HDIM,
                                      vl + hb + (size_t)kt * AKT * HDIM};
        const unsigned aoff[4] = {0, STG_K_LO, STG_V_HI, STG_V_LO};
#pragma unroll
        for (int arr = 0; arr < 4; arr++)
#pragma unroll
            for (int p = 0; p < 4; p++) {
                int i = p * 256 + tid;
                int row = i >> 4, c = i & 15;
                CP_ASYNC16(sbase + (unsigned)(sb + aoff[arr] + row * APITCH + c * 8) * 2u,
                           gs[arr] + row * HDIM + c * 8);
            }
    };

    load_kv(0, 0);
    CP_COMMIT();

    // fragment lane addressing (elems)
    const unsigned q_elem = (unsigned)((wid * 16 + (lane & 15)) * APITCH + ((lane >> 4) & 1) * 8);
    const unsigned k_elem = (unsigned)((((lane >> 4) & 1) * 8 + (lane & 7)) * APITCH
                                       + ((lane >> 3) & 1) * 8);
    const unsigned v_elem = (unsigned)(((((lane >> 3) & 1) * 8) + (lane & 7)) * APITCH
                                       + ((lane >> 4) & 1) * 8);

    float m0 = -1e30f, m1 = -1e30f, l0 = 0.f, l1 = 0.f;
    float o[16][4];
#pragma unroll
    for (int nt = 0; nt < 16; nt++)
#pragma unroll
        for (int r = 0; r < 4; r++) o[nt][r] = 0.f;

    const int qrow_warp = qt * AQT + wid * 16;
    const int nkt = 2 * qt + 2;

    for (int kt = 0; kt < nkt; kt++) {
        CP_WAIT(0);
        __syncthreads();    // stage kt ready; all warps done with stage kt-1
        if (kt + 1 < nkt) {
            load_kv((kt + 1) & 1, kt + 1);
            CP_COMMIT();
        }
        const unsigned stk = (unsigned)(SM_ST0 + (kt & 1) * STG_ELEMS);

        const bool active = (kt * AKT <= qrow_warp + 15);
        if (active) {
            // ---- S = Q K^T via LDSM fragments ----
            float sreg[8][4];
#pragma unroll
            for (int nt = 0; nt < 8; nt++)
#pragma unroll
                for (int r = 0; r < 4; r++) sreg[nt][r] = 0.f;

#pragma unroll
            for (int d8 = 0; d8 < 8; d8++) {
                unsigned ahi[4], alo[4];
                unsigned ad = sbase + (q_elem + (unsigned)(d8 * 16)) * 2u;
                LDSM_X4(ahi[0], ahi[1], ahi[2], ahi[3], ad);
                LDSM_X4(alo[0], alo[1], alo[2], alo[3], ad + (unsigned)SM_QLO * 2u);
#pragma unroll
                for (int ntp = 0; ntp < 4; ntp++) {
                    unsigned khf[4], klf[4];
                    unsigned bd = sbase + (stk + (unsigned)(ntp * 16 * APITCH) + k_elem
                                           + (unsigned)(d8 * 16)) * 2u;
                    LDSM_X4(khf[0], khf[1], khf[2], khf[3], bd);
                    LDSM_X4(klf[0], klf[1], klf[2], klf[3], bd + (unsigned)STG_K_LO * 2u);
                    mma_bf16(sreg[2 * ntp + 0], ahi, &khf[0]);
                    mma_bf16(sreg[2 * ntp + 1], ahi, &khf[2]);
                    mma_bf16(sreg[2 * ntp + 0], ahi, &klf[0]);
                    mma_bf16(sreg[2 * ntp + 1], ahi, &klf[2]);
                    mma_bf16(sreg[2 * ntp + 0], alo, &khf[0]);
                    mma_bf16(sreg[2 * ntp + 1], alo, &khf[2]);
                }
            }

            // ---- scale + causal mask ----
            const int row0 = qrow_warp + grp;
            const int row1 = row0 + 8;
#pragma unroll
            for (int nt = 0; nt < 8; nt++) {
                const int c0 = kt * AKT + nt * 8 + 2 * qid;
                const int c1 = c0 + 1;
                sreg[nt][0] = (c0 <= row0) ? sreg[nt][0] * scale : -1e30f;
                sreg[nt][1] = (c1 <= row0) ? sreg[nt][1] * scale : -1e30f;
                sreg[nt][2] = (c0 <= row1) ? sreg[nt][2] * scale : -1e30f;
                sreg[nt][3] = (c1 <= row1) ? sreg[nt][3] * scale : -1e30f;
            }

            // ---- online softmax ----
            float tm0 = -1e30f, tm1 = -1e30f;
#pragma unroll
            for (int nt = 0; nt < 8; nt++) {
                tm0 = fmaxf(tm0, fmaxf(sreg[nt][0], sreg[nt][1]));
                tm1 = fmaxf(tm1, fmaxf(sreg[nt][2], sreg[nt][3]));
            }
            tm0 = fmaxf(tm0, __shfl_xor_sync(0xffffffffu, tm0, 1));
            tm0 = fmaxf(tm0, __shfl_xor_sync(0xffffffffu, tm0, 2));
            tm1 = fmaxf(tm1, __shfl_xor_sync(0xffffffffu, tm1, 1));
            tm1 = fmaxf(tm1, __shfl_xor_sync(0xffffffffu, tm1, 2));
            const float mn0 = fmaxf(m0, tm0);
            const float mn1 = fmaxf(m1, tm1);
            const float al0 = __expf(m0 - mn0);
            const float al1 = __expf(m1 - mn1);
            m0 = mn0; m1 = mn1;
            float ps0 = 0.f, ps1 = 0.f;
#pragma unroll
            for (int nt = 0; nt < 8; nt++) {
                sreg[nt][0] = __expf(sreg[nt][0] - m0);
                sreg[nt][1] = __expf(sreg[nt][1] - m0);
                sreg[nt][2] = __expf(sreg[nt][2] - m1);
                sreg[nt][3] = __expf(sreg[nt][3] - m1);
                ps0 += sreg[nt][0] + sreg[nt][1];
                ps1 += sreg[nt][2] + sreg[nt][3];
            }
            l0 = l0 * al0 + ps0;
            l1 = l1 * al1 + ps1;
#pragma unroll
            for (int nt = 0; nt < 16; nt++) {
                o[nt][0] *= al0; o[nt][1] *= al0;
                o[nt][2] *= al1; o[nt][3] *= al1;
            }

            // ---- O += P V via ldmatrix.trans B fragments ----
#pragma unroll
            for (int c = 0; c < 4; c++) {
                unsigned phi[4], plo[4];
#pragma unroll
                for (int half = 0; half < 2; half++) {
                    const float x0 = sreg[2 * c + half][0];
                    const float x1 = sreg[2 * c + half][1];
                    const float x2 = sreg[2 * c + half][2];
                    const float x3 = sreg[2 * c + half][3];
                    __nv_bfloat16 h0 = __float2bfloat16(x0);
                    __nv_bfloat16 h1 = __float2bfloat16(x1);
                    __nv_bfloat16 h2 = __float2bfloat16(x2);
                    __nv_bfloat16 h3 = __float2bfloat16(x3);
                    phi[0 + 2 * half] = pack_bf16x2(__bfloat162float(h0), __bfloat162float(h1));
                    phi[1 + 2 * half] = pack_bf16x2(__bfloat162float(h2), __bfloat162float(h3));
                    plo[0 + 2 * half] = pack_bf16x2(x0 - __bfloat162float(h0), x1 - __bfloat162float(h1));
                    plo[1 + 2 * half] = pack_bf16x2(x2 - __bfloat162float(h2), x3 - __bfloat162float(h3));
                }
#pragma unroll
                for (int ntp = 0; ntp < 8; ntp++) {
                    unsigned vhf[4], vlf[4];
                    unsigned vd = sbase + (stk + (unsigned)STG_V_HI
                                           + (unsigned)(c * 16 * APITCH) + v_elem
                                           + (unsigned)(ntp * 16)) * 2u;
                    LDSM_X4_T(vhf[0], vhf[1], vhf[2], vhf[3], vd);
                    LDSM_X4_T(vlf[0], vlf[1], vlf[2], vlf[3],
                              vd + (unsigned)(STG_V_LO - STG_V_HI) * 2u);
                    mma_bf16(o[2 * ntp + 0], phi, &vhf[0]);
                    mma_bf16(o[2 * ntp + 1], phi, &vhf[2]);
                    mma_bf16(o[2 * ntp + 0], plo, &vhf[0]);
                    mma_bf16(o[2 * ntp + 1], plo, &vhf[2]);
                    mma_bf16(o[2 * ntp + 0], phi, &vlf[0]);
                    mma_bf16(o[2 * ntp + 1], phi, &vlf[2]);
                }
            }
        }
    }

    l0 += __shfl_xor_sync(0xffffffffu, l0, 1);
    l0 += __shfl_xor_sync(0xffffffffu, l0, 2);
    l1 += __shfl_xor_sync(0xffffffffu, l1, 1);
    l1 += __shfl_xor_sync(0xffffffffu, l1, 2);
    const float inv0 = 1.0f / l0;
    const float inv1 = 1.0f / l1;

    const int orow = b * SLEN + qt * AQT + wid * 16 + grp;
#pragma unroll
    for (int nt = 0; nt < 16; nt++) {
        const int col = h * HDIM + nt * 8 + 2 * qid;
        float v0 = o[nt][0] * inv0, v1 = o[nt][1] * inv0;
        float v2 = o[nt][2] * inv1, v3 = o[nt][3] * inv1;
        __nv_bfloat16 h0, l0b, h1, l1b, h2, l2b, h3, l3b;
        split_bf16(v0, h0, l0b); split_bf16(v1, h1, l1b);
        split_bf16(v2, h2, l2b); split_bf16(v3, h3, l3b);
        *(__nv_bfloat162*)(ctx_hi + (size_t)orow * HID + col) = __nv_bfloat162(h0, h1);
        *(__nv_bfloat162*)(ctx_lo + (size_t)orow * HID + col) = __nv_bfloat162(l0b, l1b);
        *(__nv_bfloat162*)(ctx_hi + (size_t)(orow + 8) * HID + col) = __nv_bfloat162(h2, h3);
        *(__nv_bfloat162*)(ctx_lo + (size_t)(orow + 8) * HID + col) = __nv_bfloat162(l2b, l3b);
    }
}

// ---------------- launch ----------------
extern "C" void kernel_launch(void* const* d_in, const int* in_sizes, int n_in,
                              void* d_out, int out_size)
{
    const float* hs    = (const float*)d_in[0];
    const int*   pos   = (const int*)d_in[1];
    const float* Wqkv  = (const float*)d_in[2];
    const float* bqkv  = (const float*)d_in[3];
    const float* Wo    = (const float*)d_in[4];
    float* out = (float*)d_out;

    float *qkv;
    __nv_bfloat16 *hs_hi, *hs_lo, *ctx_hi, *ctx_lo, *wqkv_hi, *wqkv_lo, *wo_hi, *wo_lo;
    __nv_bfloat16 *q_hi, *q_lo, *k_hi, *k_lo, *v_hi, *v_lo;
    cudaGetSymbolAddress((void**)&qkv, g_qkv);
    cudaGetSymbolAddress((void**)&hs_hi, g_hs_hi);
    cudaGetSymbolAddress((void**)&hs_lo, g_hs_lo);
    cudaGetSymbolAddress((void**)&ctx_hi, g_ctx_hi);
    cudaGetSymbolAddress((void**)&ctx_lo, g_ctx_lo);
    cudaGetSymbolAddress((void**)&wqkv_hi, g_wqkv_hi);
    cudaGetSymbolAddress((void**)&wqkv_lo, g_wqkv_lo);
    cudaGetSymbolAddress((void**)&wo_hi, g_wo_hi);
    cudaGetSymbolAddress((void**)&wo_lo, g_wo_lo);
    cudaGetSymbolAddress((void**)&q_hi, g_q_hi);
    cudaGetSymbolAddress((void**)&q_lo, g_q_lo);
    cudaGetSymbolAddress((void**)&k_hi, g_k_hi);
    cudaGetSymbolAddress((void**)&k_lo, g_k_lo);
    cudaGetSymbolAddress((void**)&v_hi, g_v_hi);
    cudaGetSymbolAddress((void**)&v_lo, g_v_lo);

    static int configured = 0;
    if (!configured) {
        cudaFuncSetAttribute(gemm_bf16split_kernel,
                             cudaFuncAttributeMaxDynamicSharedMemorySize, GEMM_SMEM_BYTES);
        cudaFuncSetAttribute(flash_mma_kernel,
                             cudaFuncAttributeMaxDynamicSharedMemorySize, ATT_SMEM_BYTES);
        configured = 1;
    }

    // 0) splits + weight transposes
    {
        int n4 = MROWS * HID / 4;
        split_kernel<<<(n4 + 255) / 256, 256>>>(hs, hs_hi, hs_lo, n4);
        dim3 g1(QKV_N / 32, HID / 32);
        transpose_split_kernel<<<g1, dim3(32, 8)>>>(Wqkv, wqkv_hi, wqkv_lo, HID, QKV_N);
        dim3 g2(HID / 32, HID / 32);
        transpose_split_kernel<<<g2, dim3(32, 8)>>>(Wo, wo_hi, wo_lo, HID, HID);
    }
    // 1) qkv = hs @ W_qkv + b
    {
        dim3 grid(QKV_N / BN, MROWS / BM);   // (96, 32)
        gemm_bf16split_kernel<<<grid, 256, GEMM_SMEM_BYTES>>>(
            hs_hi, hs_lo, wqkv_hi, wqkv_lo, bqkv, qkv, MROWS, QKV_N, HID);
    }
    // 2) RoPE + split + relayout
    {
        int total = MROWS * NHEAD * 64;
        rope_split_kernel<<<(total + 255) / 256, 256>>>(qkv, pos);
    }
    // 3) flash attention -> ctx hi/lo bf16
    {
        dim3 grid(SLEN / AQT, NHEAD, BATCH);   // (16, 32, 2)
        flash_mma_kernel<<<grid, 256, ATT_SMEM_BYTES>>>(q_hi, q_lo, k_hi, k_lo,
                                                        v_hi, v_lo, ctx_hi, ctx_lo);
    }
    // 4) out = ctx @ W_o
    {
        dim3 grid(HID / BN, MROWS / BM);     // (32, 32)
        gemm_bf16split_kernel<<<grid, 256, GEMM_SMEM_BYTES>>>(
            ctx_hi, ctx_lo, wo_hi, wo_lo, nullptr, out, MROWS, HID, HID);
    }
}